// round 2
// baseline (speedup 1.0000x reference)
#include <cuda_runtime.h>
#include <cstdint>
#include <cstddef>

#define BB 24
#define DD 128
#define NN 2048
#define MM 2048
#define KC 16

__device__ float g_S [(size_t)BB * NN * MM];
__device__ float g_CB[(size_t)BB * DD * MM];
__device__ float g_A [(size_t)BB * DD * NN];
__device__ float g_Bt[(size_t)BB * DD * NN];
__device__ float g_L1[BB * NN];
__device__ float g_L2[BB * MM];
__device__ float g_sq[BB * MM];
__device__ float g_sc[BB * NN];
__device__ float g_cpmx[BB * MM * 4];
__device__ float g_cps [BB * MM * 4];

// ---------------- threefry2x32, JAX partitionable, key=(0,42) -------------------
__device__ __forceinline__ uint32_t rotl32(uint32_t x, int r) {
    return __funnelshift_l(x, x, r);
}

#define TF_ROUND4(a, b, c, d)                       \
    x0 += x1; x1 = rotl32(x1, a); x1 ^= x0;         \
    x0 += x1; x1 = rotl32(x1, b); x1 ^= x0;         \
    x0 += x1; x1 = rotl32(x1, c); x1 ^= x0;         \
    x0 += x1; x1 = rotl32(x1, d); x1 ^= x0;

__device__ __forceinline__ uint32_t threefry_bits(uint32_t idx) {
    const uint32_t ks0 = 0u, ks1 = 42u;
    const uint32_t ks2 = 0x1BD11BDAu ^ ks0 ^ ks1;
    uint32_t x0 = 0u + ks0;        // hi32(count) == 0
    uint32_t x1 = idx + ks1;
    TF_ROUND4(13, 15, 26, 6)  x0 += ks1; x1 += ks2 + 1u;
    TF_ROUND4(17, 29, 16, 24) x0 += ks2; x1 += ks0 + 2u;
    TF_ROUND4(13, 15, 26, 6)  x0 += ks0; x1 += ks1 + 3u;
    TF_ROUND4(17, 29, 16, 24) x0 += ks1; x1 += ks2 + 4u;
    TF_ROUND4(13, 15, 26, 6)  x0 += ks2; x1 += ks0 + 5u;
    return x0 ^ x1;
}

__device__ __forceinline__ float dropscale(uint32_t idx, float v) {
    uint32_t bits = threefry_bits(idx);
    float u = __uint_as_float((bits >> 9) | 0x3f800000u) - 1.0f;
    return (u < 0.9f) ? v * (1.0f / 0.9f) : 0.0f;
}

// ---------------- stage 0: bias vectors -----------------------------------------
__global__ __launch_bounds__(256) void bias_kernel(const float* __restrict__ C,
                                                   const float* __restrict__ Q,
                                                   const float* __restrict__ W) {
    int b = blockIdx.y;
    int m = blockIdx.x * 256 + threadIdx.x;
    const float* X; const float* wv; float* out;
    if (blockIdx.z == 0) { X = Q + (size_t)b * DD * MM; wv = W + b * 3 * DD;      out = g_sq + b * MM; }
    else                 { X = C + (size_t)b * DD * NN; wv = W + b * 3 * DD + DD; out = g_sc + b * NN; }
    __shared__ float ws[DD];
    if (threadIdx.x < DD) ws[threadIdx.x] = wv[threadIdx.x];
    __syncthreads();
    float acc = 0.0f;
#pragma unroll 8
    for (int d = 0; d < DD; d++) acc = fmaf(ws[d], X[(size_t)d * MM + m], acc);
    out[m] = acc;
}

// ---------------- stage 1: S = C^T diag(Wm) Q + sc + sq -------------------------
__global__ __launch_bounds__(256) void gemm1_kernel(const float* __restrict__ C,
                                                    const float* __restrict__ Q,
                                                    const float* __restrict__ W) {
    int b  = blockIdx.z;
    int n0 = blockIdx.y * 128;
    int m0 = blockIdx.x * 128;
    const float* Cb = C + (size_t)b * DD * NN;
    const float* Qb = Q + (size_t)b * DD * MM;
    const float* Wm = W + b * 3 * DD + 2 * DD;
    __shared__ float As[KC][128];
    __shared__ float Bs[KC][128];
    __shared__ float wm[DD];
    int tid = threadIdx.x;
    int tx = tid & 15, ty = tid >> 4;
    if (tid < DD) wm[tid] = Wm[tid];
    __syncthreads();
    float acc[8][8] = {};
    for (int k0 = 0; k0 < DD; k0 += KC) {
#pragma unroll
        for (int i = 0; i < 2; i++) {
            int li = tid + i * 256;
            int kr = li >> 5, c4 = (li & 31) << 2;
            float w = wm[k0 + kr];
            float4 va = *reinterpret_cast<const float4*>(&Cb[(size_t)(k0 + kr) * NN + n0 + c4]);
            va.x *= w; va.y *= w; va.z *= w; va.w *= w;
            *reinterpret_cast<float4*>(&As[kr][c4]) = va;
            float4 vb = *reinterpret_cast<const float4*>(&Qb[(size_t)(k0 + kr) * MM + m0 + c4]);
            *reinterpret_cast<float4*>(&Bs[kr][c4]) = vb;
        }
        __syncthreads();
#pragma unroll
        for (int kk = 0; kk < KC; kk++) {
            float a[8], bv[8];
            *(float4*)(a)      = *(const float4*)(&As[kk][ty * 8]);
            *(float4*)(a + 4)  = *(const float4*)(&As[kk][ty * 8 + 4]);
            *(float4*)(bv)     = *(const float4*)(&Bs[kk][tx * 8]);
            *(float4*)(bv + 4) = *(const float4*)(&Bs[kk][tx * 8 + 4]);
#pragma unroll
            for (int i = 0; i < 8; i++)
#pragma unroll
                for (int j = 0; j < 8; j++)
                    acc[i][j] = fmaf(a[i], bv[j], acc[i][j]);
        }
        __syncthreads();
    }
    float* Sb = g_S + (size_t)b * NN * MM;
    float sqv[8];
#pragma unroll
    for (int j = 0; j < 8; j++) sqv[j] = g_sq[b * MM + m0 + tx * 8 + j];
#pragma unroll
    for (int i = 0; i < 8; i++) {
        float sv = g_sc[b * NN + n0 + ty * 8 + i];
        float* dst = Sb + (size_t)(n0 + ty * 8 + i) * MM + m0 + tx * 8;
        *(float4*)dst       = make_float4(acc[i][0] + sv + sqv[0], acc[i][1] + sv + sqv[1],
                                          acc[i][2] + sv + sqv[2], acc[i][3] + sv + sqv[3]);
        *(float4*)(dst + 4) = make_float4(acc[i][4] + sv + sqv[4], acc[i][5] + sv + sqv[5],
                                          acc[i][6] + sv + sqv[6], acc[i][7] + sv + sqv[7]);
    }
}

// ---------------- stage 2a: row stats -> L1 -------------------------------------
__global__ __launch_bounds__(256) void rowstats_kernel() {
    int b = blockIdx.y, n = blockIdx.x;
    const float* row = g_S + ((size_t)b * NN + n) * MM;
    __shared__ float red[256];
    int tid = threadIdx.x;
    float v[8];
    *(float4*)(v)     = *(const float4*)&row[tid * 8];
    *(float4*)(v + 4) = *(const float4*)&row[tid * 8 + 4];
    float mx = v[0];
#pragma unroll
    for (int i = 1; i < 8; i++) mx = fmaxf(mx, v[i]);
    red[tid] = mx;
    __syncthreads();
    for (int s = 128; s > 0; s >>= 1) {
        if (tid < s) red[tid] = fmaxf(red[tid], red[tid + s]);
        __syncthreads();
    }
    mx = red[0];
    __syncthreads();
    float s = 0.0f;
#pragma unroll
    for (int i = 0; i < 8; i++) s += __expf(v[i] - mx);
    red[tid] = s;
    __syncthreads();
    for (int st = 128; st > 0; st >>= 1) {
        if (tid < st) red[tid] += red[tid + st];
        __syncthreads();
    }
    if (tid == 0) g_L1[b * NN + n] = mx + logf(red[0]);
}

// ---------------- stage 2b: column stats -> L2 ----------------------------------
__global__ __launch_bounds__(256) void colstats_part_kernel() {
    int b = blockIdx.y;
    int m = blockIdx.x * 256 + threadIdx.x;
    int q = blockIdx.z;
    int n0 = q * (NN / 4), n1 = n0 + NN / 4;
    const float* Sb = g_S + (size_t)b * NN * MM;
    float mx = Sb[(size_t)n0 * MM + m];
    float s = 1.0f;
    for (int n = n0 + 1; n < n1; n++) {
        float x = Sb[(size_t)n * MM + m];
        if (x <= mx) s += __expf(x - mx);
        else { s = s * __expf(mx - x) + 1.0f; mx = x; }
    }
    g_cpmx[((size_t)b * MM + m) * 4 + q] = mx;
    g_cps [((size_t)b * MM + m) * 4 + q] = s;
}

__global__ __launch_bounds__(256) void colstats_combine_kernel() {
    int b = blockIdx.y;
    int m = blockIdx.x * 256 + threadIdx.x;
    size_t base = ((size_t)b * MM + m) * 4;
    float mx = g_cpmx[base], s = g_cps[base];
    for (int q = 1; q < 4; q++) {
        float pm = g_cpmx[base + q], ps = g_cps[base + q];
        float nm = fmaxf(mx, pm);
        s = s * __expf(mx - nm) + ps * __expf(pm - nm);
        mx = nm;
    }
    g_L2[b * MM + m] = mx + logf(s);
}

// ---------------- stage 3: CB[d][m] = sum_n C[d][n]*exp(S[n][m]-L2[m]) ----------
__global__ __launch_bounds__(256) void gemm_cb_kernel(const float* __restrict__ C) {
    int b = blockIdx.z;
    int m0 = blockIdx.x * 128;
    __shared__ float Cs[KC][DD + 4];
    __shared__ float Es[KC][128];
    __shared__ float l2[128];
    int tid = threadIdx.x;
    int tx = tid & 15, ty = tid >> 4;
    if (tid < 128) l2[tid] = g_L2[b * MM + m0 + tid];
    __syncthreads();
    float acc[8][8] = {};
    const float* Cb = C + (size_t)b * DD * NN;
    const float* Sb = g_S + (size_t)b * NN * MM;
    for (int k0 = 0; k0 < NN; k0 += KC) {
#pragma unroll
        for (int i = 0; i < 2; i++) {
            int li = tid + i * 256;
            int dr = li >> 2;
            int c4 = (li & 3) << 2;
            float4 v = *(const float4*)&Cb[(size_t)dr * NN + k0 + c4];
            Cs[c4 + 0][dr] = v.x; Cs[c4 + 1][dr] = v.y;
            Cs[c4 + 2][dr] = v.z; Cs[c4 + 3][dr] = v.w;
        }
#pragma unroll
        for (int i = 0; i < 2; i++) {
            int li = tid + i * 256;
            int kr = li >> 5, c4 = (li & 31) << 2;
            float4 v = *(const float4*)&Sb[(size_t)(k0 + kr) * MM + m0 + c4];
            Es[kr][c4 + 0] = __expf(v.x - l2[c4 + 0]);
            Es[kr][c4 + 1] = __expf(v.y - l2[c4 + 1]);
            Es[kr][c4 + 2] = __expf(v.z - l2[c4 + 2]);
            Es[kr][c4 + 3] = __expf(v.w - l2[c4 + 3]);
        }
        __syncthreads();
#pragma unroll
        for (int kk = 0; kk < KC; kk++) {
            float a[8], bv[8];
            *(float4*)(a)      = *(const float4*)(&Cs[kk][ty * 8]);
            *(float4*)(a + 4)  = *(const float4*)(&Cs[kk][ty * 8 + 4]);
            *(float4*)(bv)     = *(const float4*)(&Es[kk][tx * 8]);
            *(float4*)(bv + 4) = *(const float4*)(&Es[kk][tx * 8 + 4]);
#pragma unroll
            for (int i = 0; i < 8; i++)
#pragma unroll
                for (int j = 0; j < 8; j++)
                    acc[i][j] = fmaf(a[i], bv[j], acc[i][j]);
        }
        __syncthreads();
    }
    float* CBb = g_CB + (size_t)b * DD * MM;
#pragma unroll
    for (int i = 0; i < 8; i++) {
        float* dst = CBb + (size_t)(ty * 8 + i) * MM + m0 + tx * 8;
        *(float4*)dst       = make_float4(acc[i][0], acc[i][1], acc[i][2], acc[i][3]);
        *(float4*)(dst + 4) = make_float4(acc[i][4], acc[i][5], acc[i][6], acc[i][7]);
    }
}

// ---------------- stage 4: A / Bt: out[r][n] = sum_m X[r][m]*exp(S[n][m]-L1[n]) -
__global__ __launch_bounds__(256) void gemm_ab_kernel(const float* __restrict__ Q) {
    int b = blockIdx.z;
    int n0 = blockIdx.x * 128;
    const float* X = (blockIdx.y == 0) ? (Q + (size_t)b * DD * MM)
                                       : (g_CB + (size_t)b * DD * MM);
    float* Out = (blockIdx.y == 0) ? (g_A + (size_t)b * DD * NN)
                                   : (g_Bt + (size_t)b * DD * NN);
    __shared__ float Xs[KC][DD + 4];
    __shared__ float Es[KC][128 + 4];
    __shared__ float l1[128];
    int tid = threadIdx.x;
    int tx = tid & 15, ty = tid >> 4;
    if (tid < 128) l1[tid] = g_L1[b * NN + n0 + tid];
    __syncthreads();
    float acc[8][8] = {};
    const float* Sb = g_S + (size_t)b * NN * MM;
    for (int k0 = 0; k0 < MM; k0 += KC) {
#pragma unroll
        for (int i = 0; i < 2; i++) {
            int li = tid + i * 256;
            int rr = li >> 2;
            int c4 = (li & 3) << 2;
            float4 v = *(const float4*)&X[(size_t)rr * MM + k0 + c4];
            Xs[c4 + 0][rr] = v.x; Xs[c4 + 1][rr] = v.y;
            Xs[c4 + 2][rr] = v.z; Xs[c4 + 3][rr] = v.w;
        }
#pragma unroll
        for (int i = 0; i < 2; i++) {
            int li = tid + i * 256;
            int nr = li >> 2;
            int c4 = (li & 3) << 2;
            float4 v = *(const float4*)&Sb[(size_t)(n0 + nr) * MM + k0 + c4];
            float L = l1[nr];
            Es[c4 + 0][nr] = __expf(v.x - L);
            Es[c4 + 1][nr] = __expf(v.y - L);
            Es[c4 + 2][nr] = __expf(v.z - L);
            Es[c4 + 3][nr] = __expf(v.w - L);
        }
        __syncthreads();
#pragma unroll
        for (int kk = 0; kk < KC; kk++) {
            float a[8], bv[8];
            *(float4*)(a)      = *(const float4*)(&Xs[kk][ty * 8]);
            *(float4*)(a + 4)  = *(const float4*)(&Xs[kk][ty * 8 + 4]);
            *(float4*)(bv)     = *(const float4*)(&Es[kk][tx * 8]);
            *(float4*)(bv + 4) = *(const float4*)(&Es[kk][tx * 8 + 4]);
#pragma unroll
            for (int i = 0; i < 8; i++)
#pragma unroll
                for (int j = 0; j < 8; j++)
                    acc[i][j] = fmaf(a[i], bv[j], acc[i][j]);
        }
        __syncthreads();
    }
#pragma unroll
    for (int i = 0; i < 8; i++) {
        float* dst = Out + (size_t)(ty * 8 + i) * NN + n0 + tx * 8;
        *(float4*)dst       = make_float4(acc[i][0], acc[i][1], acc[i][2], acc[i][3]);
        *(float4*)(dst + 4) = make_float4(acc[i][4], acc[i][5], acc[i][6], acc[i][7]);
    }
}

// ---------------- stage 5: concat + dropout -------------------------------------
__device__ __forceinline__ void write_drop4(float* p, size_t idx, float4 v) {
    float4 o;
    o.x = dropscale((uint32_t)(idx + 0), v.x);
    o.y = dropscale((uint32_t)(idx + 1), v.y);
    o.z = dropscale((uint32_t)(idx + 2), v.z);
    o.w = dropscale((uint32_t)(idx + 3), v.w);
    *(float4*)p = o;
}

__global__ __launch_bounds__(256) void epilogue_kernel(const float* __restrict__ C,
                                                       float* __restrict__ out) {
    unsigned gi = blockIdx.x * 256u + threadIdx.x;
    unsigned t  = gi & 511u;
    unsigned bd = gi >> 9;
    unsigned d  = bd & 127u;
    unsigned b  = bd >> 7;
    unsigned n  = t * 4u;
    size_t src = ((size_t)(b * DD + d)) * NN + n;
    float4 c  = *(const float4*)(C    + src);
    float4 a  = *(const float4*)(g_A  + src);
    float4 bt = *(const float4*)(g_Bt + src);
    float4 ca  = make_float4(c.x * a.x,  c.y * a.y,  c.z * a.z,  c.w * a.w);
    float4 cbt = make_float4(c.x * bt.x, c.y * bt.y, c.z * bt.z, c.w * bt.w);
    size_t o0 = ((size_t)b * 4 * DD + d) * NN + n;
    const size_t st = (size_t)DD * NN;
    write_drop4(out + o0,          o0,          c);
    write_drop4(out + o0 + st,     o0 + st,     a);
    write_drop4(out + o0 + 2 * st, o0 + 2 * st, ca);
    write_drop4(out + o0 + 3 * st, o0 + 3 * st, cbt);
}

// ---------------- launch ---------------------------------------------------------
extern "C" void kernel_launch(void* const* d_in, const int* in_sizes, int n_in,
                              void* d_out, int out_size) {
    const float* C = (const float*)d_in[0];
    const float* Q = (const float*)d_in[1];
    const float* W = (const float*)d_in[2];
    float* out = (float*)d_out;

    bias_kernel<<<dim3(MM / 256, BB, 2), 256>>>(C, Q, W);
    gemm1_kernel<<<dim3(MM / 128, NN / 128, BB), 256>>>(C, Q, W);
    rowstats_kernel<<<dim3(NN, BB), 256>>>();
    colstats_part_kernel<<<dim3(MM / 256, BB, 4), 256>>>();
    colstats_combine_kernel<<<dim3(MM / 256, BB), 256>>>();
    gemm_cb_kernel<<<dim3(MM / 128, 1, BB), 256>>>(C);
    gemm_ab_kernel<<<dim3(NN / 128, 2, BB), 256>>>(Q);
    epilogue_kernel<<<dim3((BB * DD * NN / 4) / 256), 256>>>(C, out);
}

// round 5
// speedup vs baseline: 1.0705x; 1.0705x over previous
#include <cuda_runtime.h>
#include <cstdint>
#include <cstddef>

#define BB 24
#define DD 128
#define NN 2048
#define MM 2048
#define KC 16

__device__ float g_S [(size_t)BB * NN * MM];
__device__ float g_CB[(size_t)BB * DD * MM];
__device__ float g_A [(size_t)BB * DD * NN];
__device__ float g_Bt[(size_t)BB * DD * NN];
__device__ float g_L1[BB * NN];
__device__ float g_L2[BB * MM];
__device__ float g_sq[BB * MM];
__device__ float g_sc[BB * NN];
__device__ float2 g_rowp[(size_t)BB * 16 * NN];
__device__ float2 g_colp[(size_t)BB * 16 * MM];

// ---------------- packed f32x2 helpers ------------------------------------------
__device__ __forceinline__ uint64_t pk2(float lo, float hi) {
    uint64_t r; asm("mov.b64 %0,{%1,%2};" : "=l"(r) : "f"(lo), "f"(hi)); return r;
}
__device__ __forceinline__ void fma2(uint64_t& d, uint64_t a, uint64_t b) {
    asm("fma.rn.f32x2 %0,%1,%2,%0;" : "+l"(d) : "l"(a), "l"(b));
}
__device__ __forceinline__ float2 upk2(uint64_t v) {
    float2 f; asm("mov.b64 {%0,%1},%2;" : "=f"(f.x), "=f"(f.y) : "l"(v)); return f;
}

// ---------------- threefry2x32, JAX partitionable, key=(0,42) -------------------
__device__ __forceinline__ uint32_t rotl32(uint32_t x, int r) {
    return __funnelshift_l(x, x, r);
}
#define TF_ROUND4(a, b, c, d)                       \
    x0 += x1; x1 = rotl32(x1, a); x1 ^= x0;         \
    x0 += x1; x1 = rotl32(x1, b); x1 ^= x0;         \
    x0 += x1; x1 = rotl32(x1, c); x1 ^= x0;         \
    x0 += x1; x1 = rotl32(x1, d); x1 ^= x0;

__device__ __forceinline__ uint32_t threefry_bits(uint32_t idx) {
    const uint32_t ks0 = 0u, ks1 = 42u;
    const uint32_t ks2 = 0x1BD11BDAu ^ ks0 ^ ks1;
    uint32_t x0 = 0u + ks0;
    uint32_t x1 = idx + ks1;
    TF_ROUND4(13, 15, 26, 6)  x0 += ks1; x1 += ks2 + 1u;
    TF_ROUND4(17, 29, 16, 24) x0 += ks2; x1 += ks0 + 2u;
    TF_ROUND4(13, 15, 26, 6)  x0 += ks0; x1 += ks1 + 3u;
    TF_ROUND4(17, 29, 16, 24) x0 += ks1; x1 += ks2 + 4u;
    TF_ROUND4(13, 15, 26, 6)  x0 += ks2; x1 += ks0 + 5u;
    return x0 ^ x1;
}
__device__ __forceinline__ float dropscale(uint32_t idx, float v) {
    uint32_t bits = threefry_bits(idx);
    float u = __uint_as_float((bits >> 9) | 0x3f800000u) - 1.0f;
    return (u < 0.9f) ? v * (1.0f / 0.9f) : 0.0f;
}

// ---------------- stage 0: bias vectors -----------------------------------------
__global__ __launch_bounds__(256) void bias_kernel(const float* __restrict__ C,
                                                   const float* __restrict__ Q,
                                                   const float* __restrict__ W) {
    int b = blockIdx.y;
    int m = blockIdx.x * 256 + threadIdx.x;
    const float* X; const float* wv; float* out;
    if (blockIdx.z == 0) { X = Q + (size_t)b * DD * MM; wv = W + b * 3 * DD;      out = g_sq + b * MM; }
    else                 { X = C + (size_t)b * DD * NN; wv = W + b * 3 * DD + DD; out = g_sc + b * NN; }
    __shared__ float ws[DD];
    if (threadIdx.x < DD) ws[threadIdx.x] = wv[threadIdx.x];
    __syncthreads();
    float acc = 0.0f;
#pragma unroll 8
    for (int d = 0; d < DD; d++) acc = fmaf(ws[d], X[(size_t)d * MM + m], acc);
    out[m] = acc;
}

// ---------------- stage 1: S = C^T diag(Wm) Q + biases, fused tile stats --------
__global__ __launch_bounds__(256, 2) void gemm1_kernel(const float* __restrict__ C,
                                                       const float* __restrict__ Q,
                                                       const float* __restrict__ W) {
    int b  = blockIdx.z;
    int n0 = blockIdx.y * 128;
    int m0 = blockIdx.x * 128;
    const float* Cb = C + (size_t)b * DD * NN;
    const float* Qb = Q + (size_t)b * DD * MM;
    const float* Wm = W + b * 3 * DD + 2 * DD;
    __shared__ float As[KC][128];
    __shared__ float Bs[KC][128];
    __shared__ float wm[DD];
    __shared__ float red[16][128];
    __shared__ float cmx[128];
    int tid = threadIdx.x;
    int tx = tid & 15, ty = tid >> 4;
    if (tid < DD) wm[tid] = Wm[tid];
    __syncthreads();
    uint64_t acc2[8][4] = {};
    for (int k0 = 0; k0 < DD; k0 += KC) {
#pragma unroll
        for (int i = 0; i < 2; i++) {
            int li = tid + i * 256;
            int kr = li >> 5, c4 = (li & 31) << 2;
            float w = wm[k0 + kr];
            float4 va = *reinterpret_cast<const float4*>(&Cb[(size_t)(k0 + kr) * NN + n0 + c4]);
            va.x *= w; va.y *= w; va.z *= w; va.w *= w;
            *reinterpret_cast<float4*>(&As[kr][c4]) = va;
            float4 vb = *reinterpret_cast<const float4*>(&Qb[(size_t)(k0 + kr) * MM + m0 + c4]);
            *reinterpret_cast<float4*>(&Bs[kr][c4]) = vb;
        }
        __syncthreads();
#pragma unroll
        for (int kk = 0; kk < KC; kk++) {
            float a[8];
            *(float4*)(a)     = *(const float4*)(&As[kk][ty * 8]);
            *(float4*)(a + 4) = *(const float4*)(&As[kk][ty * 8 + 4]);
            ulonglong2 p0 = *(const ulonglong2*)(&Bs[kk][tx * 8]);
            ulonglong2 p1 = *(const ulonglong2*)(&Bs[kk][tx * 8 + 4]);
            uint64_t b2[4] = {p0.x, p0.y, p1.x, p1.y};
#pragma unroll
            for (int i = 0; i < 8; i++) {
                uint64_t a2 = pk2(a[i], a[i]);
#pragma unroll
                for (int j = 0; j < 4; j++) fma2(acc2[i][j], a2, b2[j]);
            }
        }
        __syncthreads();
    }
    // unpack + biases
    float vals[8][8];
    float sqv[8];
#pragma unroll
    for (int j = 0; j < 8; j++) sqv[j] = g_sq[b * MM + m0 + tx * 8 + j];
#pragma unroll
    for (int i = 0; i < 8; i++) {
        float sv = g_sc[b * NN + n0 + ty * 8 + i];
#pragma unroll
        for (int j = 0; j < 4; j++) {
            float2 f = upk2(acc2[i][j]);
            vals[i][j * 2]     = f.x + sv + sqv[j * 2];
            vals[i][j * 2 + 1] = f.y + sv + sqv[j * 2 + 1];
        }
    }
    // row partials (max,sumexp) via half-warp shuffles
    int tile_m = m0 >> 7, tile_n = n0 >> 7;
#pragma unroll
    for (int i = 0; i < 8; i++) {
        float mx = vals[i][0];
#pragma unroll
        for (int j = 1; j < 8; j++) mx = fmaxf(mx, vals[i][j]);
#pragma unroll
        for (int d = 1; d < 16; d <<= 1) mx = fmaxf(mx, __shfl_xor_sync(0xffffffffu, mx, d));
        float s = 0.0f;
#pragma unroll
        for (int j = 0; j < 8; j++) s += __expf(vals[i][j] - mx);
#pragma unroll
        for (int d = 1; d < 16; d <<= 1) s += __shfl_xor_sync(0xffffffffu, s, d);
        if (tx == 0)
            g_rowp[((size_t)(b * 16 + tile_m)) * NN + n0 + ty * 8 + i] = make_float2(mx, s);
    }
    // col partials via smem tree
    {
        float lm[8];
#pragma unroll
        for (int j = 0; j < 8; j++) {
            float m = vals[0][j];
#pragma unroll
            for (int i = 1; i < 8; i++) m = fmaxf(m, vals[i][j]);
            lm[j] = m;
        }
        *(float4*)(&red[ty][tx * 8])     = *(float4*)(lm);
        *(float4*)(&red[ty][tx * 8 + 4]) = *(float4*)(lm + 4);
        __syncthreads();
        if (tid < 128) {
            float m = red[0][tid];
#pragma unroll
            for (int t = 1; t < 16; t++) m = fmaxf(m, red[t][tid]);
            cmx[tid] = m;
        }
        __syncthreads();
        float ls[8];
#pragma unroll
        for (int j = 0; j < 8; j++) {
            float cm = cmx[tx * 8 + j];
            float s = 0.0f;
#pragma unroll
            for (int i = 0; i < 8; i++) s += __expf(vals[i][j] - cm);
            ls[j] = s;
        }
        __syncthreads();
        *(float4*)(&red[ty][tx * 8])     = *(float4*)(ls);
        *(float4*)(&red[ty][tx * 8 + 4]) = *(float4*)(ls + 4);
        __syncthreads();
        if (tid < 128) {
            float s = 0.0f;
#pragma unroll
            for (int t = 1; t < 16; t++) s += red[t][tid];
            s += red[0][tid];
            g_colp[((size_t)(b * 16 + tile_n)) * MM + m0 + tid] = make_float2(cmx[tid], s);
        }
    }
    // store S tile
    float* Sb = g_S + (size_t)b * NN * MM;
#pragma unroll
    for (int i = 0; i < 8; i++) {
        float* dst = Sb + (size_t)(n0 + ty * 8 + i) * MM + m0 + tx * 8;
        *(float4*)dst       = *(float4*)(&vals[i][0]);
        *(float4*)(dst + 4) = *(float4*)(&vals[i][4]);
    }
}

// ---------------- stage 2: combine partials -> L1, L2 ---------------------------
__global__ __launch_bounds__(256) void rowcombine_kernel() {
    int idx = blockIdx.x * 256 + threadIdx.x;   // b*NN + n
    int b = idx >> 11, n = idx & (NN - 1);
    const float2* p = g_rowp + (size_t)(b * 16) * NN + n;
    float2 f = p[0];
    float mx = f.x, s = f.y;
#pragma unroll
    for (int t = 1; t < 16; t++) {
        float2 g = p[(size_t)t * NN];
        float nm = fmaxf(mx, g.x);
        s = s * __expf(mx - nm) + g.y * __expf(g.x - nm);
        mx = nm;
    }
    g_L1[idx] = mx + logf(s);
}
__global__ __launch_bounds__(256) void colcombine_kernel() {
    int idx = blockIdx.x * 256 + threadIdx.x;   // b*MM + m
    int b = idx >> 11, m = idx & (MM - 1);
    const float2* p = g_colp + (size_t)(b * 16) * MM + m;
    float2 f = p[0];
    float mx = f.x, s = f.y;
#pragma unroll
    for (int t = 1; t < 16; t++) {
        float2 g = p[(size_t)t * MM];
        float nm = fmaxf(mx, g.x);
        s = s * __expf(mx - nm) + g.y * __expf(g.x - nm);
        mx = nm;
    }
    g_L2[idx] = mx + logf(s);
}

// ---------------- stage 3: CB[d][m] = sum_n C[d][n]*exp(S[n][m]-L2[m]) ----------
__global__ __launch_bounds__(256, 2) void gemm_cb_kernel(const float* __restrict__ C) {
    int b = blockIdx.z;
    int m0 = blockIdx.x * 128;
    __shared__ float Cs[KC][DD + 4];
    __shared__ float Es[KC][128];
    __shared__ float l2[128];
    int tid = threadIdx.x;
    int tx = tid & 15, ty = tid >> 4;
    if (tid < 128) l2[tid] = g_L2[b * MM + m0 + tid];
    __syncthreads();
    uint64_t acc2[8][4] = {};
    const float* Cb = C + (size_t)b * DD * NN;
    const float* Sb = g_S + (size_t)b * NN * MM;
    for (int k0 = 0; k0 < NN; k0 += KC) {
#pragma unroll
        for (int i = 0; i < 2; i++) {
            int li = tid + i * 256;
            int dr = li >> 2;
            int c4 = (li & 3) << 2;
            float4 v = *(const float4*)&Cb[(size_t)dr * NN + k0 + c4];
            Cs[c4 + 0][dr] = v.x; Cs[c4 + 1][dr] = v.y;
            Cs[c4 + 2][dr] = v.z; Cs[c4 + 3][dr] = v.w;
        }
#pragma unroll
        for (int i = 0; i < 2; i++) {
            int li = tid + i * 256;
            int kr = li >> 5, c4 = (li & 31) << 2;
            float4 v = *(const float4*)&Sb[(size_t)(k0 + kr) * MM + m0 + c4];
            Es[kr][c4 + 0] = __expf(v.x - l2[c4 + 0]);
            Es[kr][c4 + 1] = __expf(v.y - l2[c4 + 1]);
            Es[kr][c4 + 2] = __expf(v.z - l2[c4 + 2]);
            Es[kr][c4 + 3] = __expf(v.w - l2[c4 + 3]);
        }
        __syncthreads();
#pragma unroll
        for (int kk = 0; kk < KC; kk++) {
            float a[8];
            *(float4*)(a)     = *(const float4*)(&Cs[kk][ty * 8]);
            *(float4*)(a + 4) = *(const float4*)(&Cs[kk][ty * 8 + 4]);
            ulonglong2 p0 = *(const ulonglong2*)(&Es[kk][tx * 8]);
            ulonglong2 p1 = *(const ulonglong2*)(&Es[kk][tx * 8 + 4]);
            uint64_t b2[4] = {p0.x, p0.y, p1.x, p1.y};
#pragma unroll
            for (int i = 0; i < 8; i++) {
                uint64_t a2 = pk2(a[i], a[i]);
#pragma unroll
                for (int j = 0; j < 4; j++) fma2(acc2[i][j], a2, b2[j]);
            }
        }
        __syncthreads();
    }
    float* CBb = g_CB + (size_t)b * DD * MM;
#pragma unroll
    for (int i = 0; i < 8; i++) {
        float2 f0 = upk2(acc2[i][0]), f1 = upk2(acc2[i][1]);
        float2 f2 = upk2(acc2[i][2]), f3 = upk2(acc2[i][3]);
        float* dst = CBb + (size_t)(ty * 8 + i) * MM + m0 + tx * 8;
        *(float4*)dst       = make_float4(f0.x, f0.y, f1.x, f1.y);
        *(float4*)(dst + 4) = make_float4(f2.x, f2.y, f3.x, f3.y);
    }
}

// ---------------- stage 4: A / Bt: out[r][n] = sum_m X[r][m]*exp(S[n][m]-L1[n]) -
__global__ __launch_bounds__(256, 2) void gemm_ab_kernel(const float* __restrict__ Q) {
    int b = blockIdx.z;
    int n0 = blockIdx.x * 128;
    const float* X = (blockIdx.y == 0) ? (Q + (size_t)b * DD * MM)
                                       : (g_CB + (size_t)b * DD * MM);
    float* Out = (blockIdx.y == 0) ? (g_A + (size_t)b * DD * NN)
                                   : (g_Bt + (size_t)b * DD * NN);
    __shared__ float Xs[KC][DD + 4];
    __shared__ float Es[KC][128 + 4];
    __shared__ float l1[128];
    int tid = threadIdx.x;
    int tx = tid & 15, ty = tid >> 4;
    if (tid < 128) l1[tid] = g_L1[b * NN + n0 + tid];
    __syncthreads();
    uint64_t acc2[8][4] = {};
    const float* Sb = g_S + (size_t)b * NN * MM;
    for (int k0 = 0; k0 < MM; k0 += KC) {
#pragma unroll
        for (int i = 0; i < 2; i++) {
            int li = tid + i * 256;
            int rr = li >> 2;
            int c4 = (li & 3) << 2;
            float4 v = *(const float4*)&X[(size_t)rr * MM + k0 + c4];
            Xs[c4 + 0][rr] = v.x; Xs[c4 + 1][rr] = v.y;
            Xs[c4 + 2][rr] = v.z; Xs[c4 + 3][rr] = v.w;
        }
#pragma unroll
        for (int i = 0; i < 2; i++) {
            int li = tid + i * 256;
            int nr = li >> 2;
            int c4 = (li & 3) << 2;
            float4 v = *(const float4*)&Sb[(size_t)(n0 + nr) * MM + k0 + c4];
            float L = l1[nr];
            Es[c4 + 0][nr] = __expf(v.x - L);
            Es[c4 + 1][nr] = __expf(v.y - L);
            Es[c4 + 2][nr] = __expf(v.z - L);
            Es[c4 + 3][nr] = __expf(v.w - L);
        }
        __syncthreads();
#pragma unroll
        for (int kk = 0; kk < KC; kk++) {
            float a[8];
            *(float4*)(a)     = *(const float4*)(&Xs[kk][ty * 8]);
            *(float4*)(a + 4) = *(const float4*)(&Xs[kk][ty * 8 + 4]);
            ulonglong2 p0 = *(const ulonglong2*)(&Es[kk][tx * 8]);
            ulonglong2 p1 = *(const ulonglong2*)(&Es[kk][tx * 8 + 4]);
            uint64_t b2[4] = {p0.x, p0.y, p1.x, p1.y};
#pragma unroll
            for (int i = 0; i < 8; i++) {
                uint64_t a2 = pk2(a[i], a[i]);
#pragma unroll
                for (int j = 0; j < 4; j++) fma2(acc2[i][j], a2, b2[j]);
            }
        }
        __syncthreads();
    }
#pragma unroll
    for (int i = 0; i < 8; i++) {
        float2 f0 = upk2(acc2[i][0]), f1 = upk2(acc2[i][1]);
        float2 f2 = upk2(acc2[i][2]), f3 = upk2(acc2[i][3]);
        float* dst = Out + (size_t)(ty * 8 + i) * NN + n0 + tx * 8;
        *(float4*)dst       = make_float4(f0.x, f0.y, f1.x, f1.y);
        *(float4*)(dst + 4) = make_float4(f2.x, f2.y, f3.x, f3.y);
    }
}

// ---------------- stage 5: concat + dropout -------------------------------------
__device__ __forceinline__ void write_drop4(float* p, size_t idx, float4 v) {
    float4 o;
    o.x = dropscale((uint32_t)(idx + 0), v.x);
    o.y = dropscale((uint32_t)(idx + 1), v.y);
    o.z = dropscale((uint32_t)(idx + 2), v.z);
    o.w = dropscale((uint32_t)(idx + 3), v.w);
    *(float4*)p = o;
}

__global__ __launch_bounds__(256) void epilogue_kernel(const float* __restrict__ C,
                                                       float* __restrict__ out) {
    unsigned gi = blockIdx.x * 256u + threadIdx.x;
    unsigned t  = gi & 511u;
    unsigned bd = gi >> 9;
    unsigned d  = bd & 127u;
    unsigned b  = bd >> 7;
    unsigned n  = t * 4u;
    size_t src = ((size_t)(b * DD + d)) * NN + n;
    float4 c  = *(const float4*)(C    + src);
    float4 a  = *(const float4*)(g_A  + src);
    float4 bt = *(const float4*)(g_Bt + src);
    float4 ca  = make_float4(c.x * a.x,  c.y * a.y,  c.z * a.z,  c.w * a.w);
    float4 cbt = make_float4(c.x * bt.x, c.y * bt.y, c.z * bt.z, c.w * bt.w);
    size_t o0 = ((size_t)b * 4 * DD + d) * NN + n;
    const size_t st = (size_t)DD * NN;
    write_drop4(out + o0,          o0,          c);
    write_drop4(out + o0 + st,     o0 + st,     a);
    write_drop4(out + o0 + 2 * st, o0 + 2 * st, ca);
    write_drop4(out + o0 + 3 * st, o0 + 3 * st, cbt);
}

// ---------------- launch ---------------------------------------------------------
extern "C" void kernel_launch(void* const* d_in, const int* in_sizes, int n_in,
                              void* d_out, int out_size) {
    const float* C = (const float*)d_in[0];
    const float* Q = (const float*)d_in[1];
    const float* W = (const float*)d_in[2];
    float* out = (float*)d_out;

    bias_kernel<<<dim3(MM / 256, BB, 2), 256>>>(C, Q, W);
    gemm1_kernel<<<dim3(MM / 128, NN / 128, BB), 256>>>(C, Q, W);
    rowcombine_kernel<<<dim3((BB * NN) / 256), 256>>>();
    colcombine_kernel<<<dim3((BB * MM) / 256), 256>>>();
    gemm_cb_kernel<<<dim3(MM / 128, 1, BB), 256>>>(C);
    gemm_ab_kernel<<<dim3(NN / 128, 2, BB), 256>>>(Q);
    epilogue_kernel<<<dim3((BB * DD * NN / 4) / 256), 256>>>(C, out);
}

// round 6
// speedup vs baseline: 1.0716x; 1.0011x over previous
#include <cuda_runtime.h>
#include <cstdint>
#include <cstddef>

#define BB 24
#define DD 128
#define NN 2048
#define MM 2048
#define KC 16

__device__ float g_S [(size_t)BB * NN * MM];
__device__ float g_CB[(size_t)BB * DD * MM];
__device__ float g_A [(size_t)BB * DD * NN];
__device__ float g_Bt[(size_t)BB * DD * NN];
__device__ float g_L1[BB * NN];
__device__ float g_L2[BB * MM];
__device__ float g_sq[BB * MM];
__device__ float g_sc[BB * NN];
__device__ float2 g_rowp[(size_t)BB * 16 * NN];
__device__ float2 g_colp[(size_t)BB * 16 * MM];

// ---------------- packed f32x2 helpers ------------------------------------------
__device__ __forceinline__ uint64_t pk2(float lo, float hi) {
    uint64_t r; asm("mov.b64 %0,{%1,%2};" : "=l"(r) : "f"(lo), "f"(hi)); return r;
}
__device__ __forceinline__ void fma2(uint64_t& d, uint64_t a, uint64_t b) {
    asm("fma.rn.f32x2 %0,%1,%2,%0;" : "+l"(d) : "l"(a), "l"(b));
}
__device__ __forceinline__ float2 upk2(uint64_t v) {
    float2 f; asm("mov.b64 {%0,%1},%2;" : "=f"(f.x), "=f"(f.y) : "l"(v)); return f;
}

// ---------------- threefry2x32, JAX partitionable, key=(0,42) -------------------
__device__ __forceinline__ uint32_t rotl32(uint32_t x, int r) {
    return __funnelshift_l(x, x, r);
}
#define TF_ROUND4(a, b, c, d)                       \
    x0 += x1; x1 = rotl32(x1, a); x1 ^= x0;         \
    x0 += x1; x1 = rotl32(x1, b); x1 ^= x0;         \
    x0 += x1; x1 = rotl32(x1, c); x1 ^= x0;         \
    x0 += x1; x1 = rotl32(x1, d); x1 ^= x0;

__device__ __forceinline__ uint32_t threefry_bits(uint32_t idx) {
    const uint32_t ks0 = 0u, ks1 = 42u;
    const uint32_t ks2 = 0x1BD11BDAu ^ ks0 ^ ks1;
    uint32_t x0 = 0u + ks0;
    uint32_t x1 = idx + ks1;
    TF_ROUND4(13, 15, 26, 6)  x0 += ks1; x1 += ks2 + 1u;
    TF_ROUND4(17, 29, 16, 24) x0 += ks2; x1 += ks0 + 2u;
    TF_ROUND4(13, 15, 26, 6)  x0 += ks0; x1 += ks1 + 3u;
    TF_ROUND4(17, 29, 16, 24) x0 += ks1; x1 += ks2 + 4u;
    TF_ROUND4(13, 15, 26, 6)  x0 += ks2; x1 += ks0 + 5u;
    return x0 ^ x1;
}
__device__ __forceinline__ float dropscale(uint32_t idx, float v) {
    uint32_t bits = threefry_bits(idx);
    float u = __uint_as_float((bits >> 9) | 0x3f800000u) - 1.0f;
    return (u < 0.9f) ? v * (1.0f / 0.9f) : 0.0f;
}

// ---------------- stage 0: bias vectors -----------------------------------------
__global__ __launch_bounds__(256) void bias_kernel(const float* __restrict__ C,
                                                   const float* __restrict__ Q,
                                                   const float* __restrict__ W) {
    int b = blockIdx.y;
    int m = blockIdx.x * 256 + threadIdx.x;
    const float* X; const float* wv; float* out;
    if (blockIdx.z == 0) { X = Q + (size_t)b * DD * MM; wv = W + b * 3 * DD;      out = g_sq + b * MM; }
    else                 { X = C + (size_t)b * DD * NN; wv = W + b * 3 * DD + DD; out = g_sc + b * NN; }
    __shared__ float ws[DD];
    if (threadIdx.x < DD) ws[threadIdx.x] = wv[threadIdx.x];
    __syncthreads();
    float acc = 0.0f;
#pragma unroll 8
    for (int d = 0; d < DD; d++) acc = fmaf(ws[d], X[(size_t)d * MM + m], acc);
    out[m] = acc;
}

// ---------------- stage 1: S = C^T diag(Wm) Q + biases, fused tile stats --------
__global__ __launch_bounds__(256, 2) void gemm1_kernel(const float* __restrict__ C,
                                                       const float* __restrict__ Q,
                                                       const float* __restrict__ W) {
    int b  = blockIdx.z;
    int n0 = blockIdx.y * 128;
    int m0 = blockIdx.x * 128;
    const float* Cb = C + (size_t)b * DD * NN;
    const float* Qb = Q + (size_t)b * DD * MM;
    const float* Wm = W + b * 3 * DD + 2 * DD;
    __shared__ float As[KC][128];
    __shared__ float Bs[KC][128];
    __shared__ float wm[DD];
    __shared__ float red[16][128];
    __shared__ float cmx[128];
    int tid = threadIdx.x;
    int tx = tid & 15, ty = tid >> 4;
    if (tid < DD) wm[tid] = Wm[tid];
    __syncthreads();
    uint64_t acc2[8][4] = {};
    for (int k0 = 0; k0 < DD; k0 += KC) {
#pragma unroll
        for (int i = 0; i < 2; i++) {
            int li = tid + i * 256;
            int kr = li >> 5, c4 = (li & 31) << 2;
            float w = wm[k0 + kr];
            float4 va = *reinterpret_cast<const float4*>(&Cb[(size_t)(k0 + kr) * NN + n0 + c4]);
            va.x *= w; va.y *= w; va.z *= w; va.w *= w;
            *reinterpret_cast<float4*>(&As[kr][c4]) = va;
            float4 vb = *reinterpret_cast<const float4*>(&Qb[(size_t)(k0 + kr) * MM + m0 + c4]);
            *reinterpret_cast<float4*>(&Bs[kr][c4]) = vb;
        }
        __syncthreads();
#pragma unroll
        for (int kk = 0; kk < KC; kk++) {
            float a[8];
            *(float4*)(a)     = *(const float4*)(&As[kk][ty * 8]);
            *(float4*)(a + 4) = *(const float4*)(&As[kk][ty * 8 + 4]);
            ulonglong2 p0 = *(const ulonglong2*)(&Bs[kk][tx * 8]);
            ulonglong2 p1 = *(const ulonglong2*)(&Bs[kk][tx * 8 + 4]);
            uint64_t b2[4] = {p0.x, p0.y, p1.x, p1.y};
#pragma unroll
            for (int i = 0; i < 8; i++) {
                uint64_t a2 = pk2(a[i], a[i]);
#pragma unroll
                for (int j = 0; j < 4; j++) fma2(acc2[i][j], a2, b2[j]);
            }
        }
        __syncthreads();
    }
    // unpack + biases
    float vals[8][8];
    float sqv[8];
#pragma unroll
    for (int j = 0; j < 8; j++) sqv[j] = g_sq[b * MM + m0 + tx * 8 + j];
#pragma unroll
    for (int i = 0; i < 8; i++) {
        float sv = g_sc[b * NN + n0 + ty * 8 + i];
#pragma unroll
        for (int j = 0; j < 4; j++) {
            float2 f = upk2(acc2[i][j]);
            vals[i][j * 2]     = f.x + sv + sqv[j * 2];
            vals[i][j * 2 + 1] = f.y + sv + sqv[j * 2 + 1];
        }
    }
    // row partials (max,sumexp) via half-warp shuffles
    int tile_m = m0 >> 7, tile_n = n0 >> 7;
#pragma unroll
    for (int i = 0; i < 8; i++) {
        float mx = vals[i][0];
#pragma unroll
        for (int j = 1; j < 8; j++) mx = fmaxf(mx, vals[i][j]);
#pragma unroll
        for (int d = 1; d < 16; d <<= 1) mx = fmaxf(mx, __shfl_xor_sync(0xffffffffu, mx, d));
        float s = 0.0f;
#pragma unroll
        for (int j = 0; j < 8; j++) s += __expf(vals[i][j] - mx);
#pragma unroll
        for (int d = 1; d < 16; d <<= 1) s += __shfl_xor_sync(0xffffffffu, s, d);
        if (tx == 0)
            g_rowp[((size_t)(b * 16 + tile_m)) * NN + n0 + ty * 8 + i] = make_float2(mx, s);
    }
    // col partials via smem tree
    {
        float lm[8];
#pragma unroll
        for (int j = 0; j < 8; j++) {
            float m = vals[0][j];
#pragma unroll
            for (int i = 1; i < 8; i++) m = fmaxf(m, vals[i][j]);
            lm[j] = m;
        }
        *(float4*)(&red[ty][tx * 8])     = *(float4*)(lm);
        *(float4*)(&red[ty][tx * 8 + 4]) = *(float4*)(lm + 4);
        __syncthreads();
        if (tid < 128) {
            float m = red[0][tid];
#pragma unroll
            for (int t = 1; t < 16; t++) m = fmaxf(m, red[t][tid]);
            cmx[tid] = m;
        }
        __syncthreads();
        float ls[8];
#pragma unroll
        for (int j = 0; j < 8; j++) {
            float cm = cmx[tx * 8 + j];
            float s = 0.0f;
#pragma unroll
            for (int i = 0; i < 8; i++) s += __expf(vals[i][j] - cm);
            ls[j] = s;
        }
        __syncthreads();
        *(float4*)(&red[ty][tx * 8])     = *(float4*)(ls);
        *(float4*)(&red[ty][tx * 8 + 4]) = *(float4*)(ls + 4);
        __syncthreads();
        if (tid < 128) {
            float s = 0.0f;
#pragma unroll
            for (int t = 1; t < 16; t++) s += red[t][tid];
            s += red[0][tid];
            g_colp[((size_t)(b * 16 + tile_n)) * MM + m0 + tid] = make_float2(cmx[tid], s);
        }
    }
    // store S tile
    float* Sb = g_S + (size_t)b * NN * MM;
#pragma unroll
    for (int i = 0; i < 8; i++) {
        float* dst = Sb + (size_t)(n0 + ty * 8 + i) * MM + m0 + tx * 8;
        *(float4*)dst       = *(float4*)(&vals[i][0]);
        *(float4*)(dst + 4) = *(float4*)(&vals[i][4]);
    }
}

// ---------------- stage 2: combine partials -> L1, L2 ---------------------------
__global__ __launch_bounds__(256) void rowcombine_kernel() {
    int idx = blockIdx.x * 256 + threadIdx.x;   // b*NN + n
    int b = idx >> 11, n = idx & (NN - 1);
    const float2* p = g_rowp + (size_t)(b * 16) * NN + n;
    float2 f = p[0];
    float mx = f.x, s = f.y;
#pragma unroll
    for (int t = 1; t < 16; t++) {
        float2 g = p[(size_t)t * NN];
        float nm = fmaxf(mx, g.x);
        s = s * __expf(mx - nm) + g.y * __expf(g.x - nm);
        mx = nm;
    }
    g_L1[idx] = mx + logf(s);
}
__global__ __launch_bounds__(256) void colcombine_kernel() {
    int idx = blockIdx.x * 256 + threadIdx.x;   // b*MM + m
    int b = idx >> 11, m = idx & (MM - 1);
    const float2* p = g_colp + (size_t)(b * 16) * MM + m;
    float2 f = p[0];
    float mx = f.x, s = f.y;
#pragma unroll
    for (int t = 1; t < 16; t++) {
        float2 g = p[(size_t)t * MM];
        float nm = fmaxf(mx, g.x);
        s = s * __expf(mx - nm) + g.y * __expf(g.x - nm);
        mx = nm;
    }
    g_L2[idx] = mx + logf(s);
}

// ---------------- stage 3: CB[d][m] = sum_n C[d][n]*exp(S[n][m]-L2[m]) ----------
__global__ __launch_bounds__(256, 2) void gemm_cb_kernel(const float* __restrict__ C) {
    int b = blockIdx.z;
    int m0 = blockIdx.x * 128;
    __shared__ float Cs[KC][DD + 4];
    __shared__ float Es[KC][128];
    __shared__ float l2[128];
    int tid = threadIdx.x;
    int tx = tid & 15, ty = tid >> 4;
    if (tid < 128) l2[tid] = g_L2[b * MM + m0 + tid];
    __syncthreads();
    uint64_t acc2[8][4] = {};
    const float* Cb = C + (size_t)b * DD * NN;
    const float* Sb = g_S + (size_t)b * NN * MM;
    for (int k0 = 0; k0 < NN; k0 += KC) {
#pragma unroll
        for (int i = 0; i < 2; i++) {
            int li = tid + i * 256;
            int dr = li >> 2;
            int c4 = (li & 3) << 2;
            float4 v = *(const float4*)&Cb[(size_t)dr * NN + k0 + c4];
            Cs[c4 + 0][dr] = v.x; Cs[c4 + 1][dr] = v.y;
            Cs[c4 + 2][dr] = v.z; Cs[c4 + 3][dr] = v.w;
        }
#pragma unroll
        for (int i = 0; i < 2; i++) {
            int li = tid + i * 256;
            int kr = li >> 5, c4 = (li & 31) << 2;
            float4 v = *(const float4*)&Sb[(size_t)(k0 + kr) * MM + m0 + c4];
            Es[kr][c4 + 0] = __expf(v.x - l2[c4 + 0]);
            Es[kr][c4 + 1] = __expf(v.y - l2[c4 + 1]);
            Es[kr][c4 + 2] = __expf(v.z - l2[c4 + 2]);
            Es[kr][c4 + 3] = __expf(v.w - l2[c4 + 3]);
        }
        __syncthreads();
#pragma unroll
        for (int kk = 0; kk < KC; kk++) {
            float a[8];
            *(float4*)(a)     = *(const float4*)(&Cs[kk][ty * 8]);
            *(float4*)(a + 4) = *(const float4*)(&Cs[kk][ty * 8 + 4]);
            ulonglong2 p0 = *(const ulonglong2*)(&Es[kk][tx * 8]);
            ulonglong2 p1 = *(const ulonglong2*)(&Es[kk][tx * 8 + 4]);
            uint64_t b2[4] = {p0.x, p0.y, p1.x, p1.y};
#pragma unroll
            for (int i = 0; i < 8; i++) {
                uint64_t a2 = pk2(a[i], a[i]);
#pragma unroll
                for (int j = 0; j < 4; j++) fma2(acc2[i][j], a2, b2[j]);
            }
        }
        __syncthreads();
    }
    float* CBb = g_CB + (size_t)b * DD * MM;
#pragma unroll
    for (int i = 0; i < 8; i++) {
        float2 f0 = upk2(acc2[i][0]), f1 = upk2(acc2[i][1]);
        float2 f2 = upk2(acc2[i][2]), f3 = upk2(acc2[i][3]);
        float* dst = CBb + (size_t)(ty * 8 + i) * MM + m0 + tx * 8;
        *(float4*)dst       = make_float4(f0.x, f0.y, f1.x, f1.y);
        *(float4*)(dst + 4) = make_float4(f2.x, f2.y, f3.x, f3.y);
    }
}

// ---------------- stage 4: A / Bt: out[r][n] = sum_m X[r][m]*exp(S[n][m]-L1[n]) -
__global__ __launch_bounds__(256, 2) void gemm_ab_kernel(const float* __restrict__ Q) {
    int b = blockIdx.z;
    int n0 = blockIdx.x * 128;
    const float* X = (blockIdx.y == 0) ? (Q + (size_t)b * DD * MM)
                                       : (g_CB + (size_t)b * DD * MM);
    float* Out = (blockIdx.y == 0) ? (g_A + (size_t)b * DD * NN)
                                   : (g_Bt + (size_t)b * DD * NN);
    __shared__ float Xs[KC][DD + 4];
    __shared__ float Es[KC][128 + 4];
    __shared__ float l1[128];
    int tid = threadIdx.x;
    int tx = tid & 15, ty = tid >> 4;
    if (tid < 128) l1[tid] = g_L1[b * NN + n0 + tid];
    __syncthreads();
    uint64_t acc2[8][4] = {};
    const float* Sb = g_S + (size_t)b * NN * MM;
    for (int k0 = 0; k0 < MM; k0 += KC) {
#pragma unroll
        for (int i = 0; i < 2; i++) {
            int li = tid + i * 256;
            int rr = li >> 2;
            int c4 = (li & 3) << 2;
            float4 v = *(const float4*)&X[(size_t)rr * MM + k0 + c4];
            Xs[c4 + 0][rr] = v.x; Xs[c4 + 1][rr] = v.y;
            Xs[c4 + 2][rr] = v.z; Xs[c4 + 3][rr] = v.w;
        }
#pragma unroll
        for (int i = 0; i < 2; i++) {
            int li = tid + i * 256;
            int nr = li >> 2;
            int c4 = (li & 3) << 2;
            float4 v = *(const float4*)&Sb[(size_t)(n0 + nr) * MM + k0 + c4];
            float L = l1[nr];
            Es[c4 + 0][nr] = __expf(v.x - L);
            Es[c4 + 1][nr] = __expf(v.y - L);
            Es[c4 + 2][nr] = __expf(v.z - L);
            Es[c4 + 3][nr] = __expf(v.w - L);
        }
        __syncthreads();
#pragma unroll
        for (int kk = 0; kk < KC; kk++) {
            float a[8];
            *(float4*)(a)     = *(const float4*)(&Xs[kk][ty * 8]);
            *(float4*)(a + 4) = *(const float4*)(&Xs[kk][ty * 8 + 4]);
            ulonglong2 p0 = *(const ulonglong2*)(&Es[kk][tx * 8]);
            ulonglong2 p1 = *(const ulonglong2*)(&Es[kk][tx * 8 + 4]);
            uint64_t b2[4] = {p0.x, p0.y, p1.x, p1.y};
#pragma unroll
            for (int i = 0; i < 8; i++) {
                uint64_t a2 = pk2(a[i], a[i]);
#pragma unroll
                for (int j = 0; j < 4; j++) fma2(acc2[i][j], a2, b2[j]);
            }
        }
        __syncthreads();
    }
#pragma unroll
    for (int i = 0; i < 8; i++) {
        float2 f0 = upk2(acc2[i][0]), f1 = upk2(acc2[i][1]);
        float2 f2 = upk2(acc2[i][2]), f3 = upk2(acc2[i][3]);
        float* dst = Out + (size_t)(ty * 8 + i) * NN + n0 + tx * 8;
        *(float4*)dst       = make_float4(f0.x, f0.y, f1.x, f1.y);
        *(float4*)(dst + 4) = make_float4(f2.x, f2.y, f3.x, f3.y);
    }
}

// ---------------- stage 5: concat + dropout -------------------------------------
__device__ __forceinline__ void write_drop4(float* p, size_t idx, float4 v) {
    float4 o;
    o.x = dropscale((uint32_t)(idx + 0), v.x);
    o.y = dropscale((uint32_t)(idx + 1), v.y);
    o.z = dropscale((uint32_t)(idx + 2), v.z);
    o.w = dropscale((uint32_t)(idx + 3), v.w);
    *(float4*)p = o;
}

__global__ __launch_bounds__(256) void epilogue_kernel(const float* __restrict__ C,
                                                       float* __restrict__ out) {
    unsigned gi = blockIdx.x * 256u + threadIdx.x;
    unsigned t  = gi & 511u;
    unsigned bd = gi >> 9;
    unsigned d  = bd & 127u;
    unsigned b  = bd >> 7;
    unsigned n  = t * 4u;
    size_t src = ((size_t)(b * DD + d)) * NN + n;
    float4 c  = *(const float4*)(C    + src);
    float4 a  = *(const float4*)(g_A  + src);
    float4 bt = *(const float4*)(g_Bt + src);
    float4 ca  = make_float4(c.x * a.x,  c.y * a.y,  c.z * a.z,  c.w * a.w);
    float4 cbt = make_float4(c.x * bt.x, c.y * bt.y, c.z * bt.z, c.w * bt.w);
    size_t o0 = ((size_t)b * 4 * DD + d) * NN + n;
    const size_t st = (size_t)DD * NN;
    write_drop4(out + o0,          o0,          c);
    write_drop4(out + o0 + st,     o0 + st,     a);
    write_drop4(out + o0 + 2 * st, o0 + 2 * st, ca);
    write_drop4(out + o0 + 3 * st, o0 + 3 * st, cbt);
}

// ---------------- launch ---------------------------------------------------------
extern "C" void kernel_launch(void* const* d_in, const int* in_sizes, int n_in,
                              void* d_out, int out_size) {
    const float* C = (const float*)d_in[0];
    const float* Q = (const float*)d_in[1];
    const float* W = (const float*)d_in[2];
    float* out = (float*)d_out;

    bias_kernel<<<dim3(MM / 256, BB, 2), 256>>>(C, Q, W);
    gemm1_kernel<<<dim3(MM / 128, NN / 128, BB), 256>>>(C, Q, W);
    rowcombine_kernel<<<dim3((BB * NN) / 256), 256>>>();
    colcombine_kernel<<<dim3((BB * MM) / 256), 256>>>();
    gemm_cb_kernel<<<dim3(MM / 128, 1, BB), 256>>>(C);
    gemm_ab_kernel<<<dim3(NN / 128, 2, BB), 256>>>(Q);
    epilogue_kernel<<<dim3((BB * DD * NN / 4) / 256), 256>>>(C, out);
}

// round 8
// speedup vs baseline: 1.5080x; 1.4072x over previous
#include <cuda_runtime.h>
#include <cuda_bf16.h>
#include <cstdint>
#include <cstddef>

#define BB 24
#define DD 128
#define NN 2048
#define MM 2048
#define KC 16
#define KB 32

__device__ float g_S [(size_t)BB * NN * MM];
__device__ float g_A [(size_t)BB * DD * NN];
__device__ float g_Bt[(size_t)BB * DD * NN];
__device__ float g_L1[BB * NN];
__device__ float g_L2[BB * MM];
__device__ float g_sq[BB * MM];
__device__ float g_sc[BB * NN];
__device__ float2 g_rowp[(size_t)BB * 16 * NN];
__device__ float2 g_colp[(size_t)BB * 16 * MM];
__device__ __nv_bfloat16 g_Chi[(size_t)BB * DD * NN];
__device__ __nv_bfloat16 g_Clo[(size_t)BB * DD * NN];
__device__ __nv_bfloat16 g_Qhi[(size_t)BB * DD * MM];
__device__ __nv_bfloat16 g_Qlo[(size_t)BB * DD * MM];
__device__ __nv_bfloat16 g_CBhi[(size_t)BB * DD * MM];
__device__ __nv_bfloat16 g_CBlo[(size_t)BB * DD * MM];

// ---- f32x2 helpers (gemm1) ----
__device__ __forceinline__ uint64_t pk2(float lo, float hi) {
    uint64_t r; asm("mov.b64 %0,{%1,%2};" : "=l"(r) : "f"(lo), "f"(hi)); return r;
}
__device__ __forceinline__ void fma2(uint64_t& d, uint64_t a, uint64_t b) {
    asm("fma.rn.f32x2 %0,%1,%2,%0;" : "+l"(d) : "l"(a), "l"(b));
}
__device__ __forceinline__ float2 upk2(uint64_t v) {
    float2 f; asm("mov.b64 {%0,%1},%2;" : "=f"(f.x), "=f"(f.y) : "l"(v)); return f;
}

// ---- warp mma (baseline sm_80+ HMMA, works on plain sm_103) ----
__device__ __forceinline__ void mma16816(float* c, const uint32_t* a, const uint32_t* b) {
    asm volatile("mma.sync.aligned.m16n8k16.row.col.f32.bf16.bf16.f32 "
                 "{%0,%1,%2,%3},{%4,%5,%6,%7},{%8,%9},{%0,%1,%2,%3};"
                 : "+f"(c[0]), "+f"(c[1]), "+f"(c[2]), "+f"(c[3])
                 : "r"(a[0]), "r"(a[1]), "r"(a[2]), "r"(a[3]), "r"(b[0]), "r"(b[1]));
}

__device__ __forceinline__ void splitf(float x, uint16_t& h, uint16_t& l) {
    __nv_bfloat16 bh = __float2bfloat16_rn(x);
    float r = x - __bfloat162float(bh);
    __nv_bfloat16 bl = __float2bfloat16_rn(r);
    h = __bfloat16_as_ushort(bh); l = __bfloat16_as_ushort(bl);
}
__device__ __forceinline__ uint32_t packsplit_hi(float a, float b) {
    uint16_t h0, l0, h1, l1; splitf(a, h0, l0); splitf(b, h1, l1);
    return (uint32_t)h0 | ((uint32_t)h1 << 16);
}
__device__ __forceinline__ uint32_t packsplit_lo(float a, float b) {
    uint16_t h0, l0, h1, l1; splitf(a, h0, l0); splitf(b, h1, l1);
    return (uint32_t)l0 | ((uint32_t)l1 << 16);
}
// fast exp on FMA pipe (rel err ~2.4e-6)
__device__ __forceinline__ float fexp(float x) {
    float t = fmaxf(x * 1.4426950408889634f, -126.0f);
    float kf = t + 12582912.0f;
    float fi = kf - 12582912.0f;
    float f = t - fi;
    float p = 1.3333558146e-3f;
    p = fmaf(p, f, 9.6181291076e-3f);
    p = fmaf(p, f, 5.5504108665e-2f);
    p = fmaf(p, f, 2.4022650696e-1f);
    p = fmaf(p, f, 6.9314718056e-1f);
    p = fmaf(p, f, 1.0f);
    return __int_as_float(__float_as_int(p) + (((int)fi) << 23));
}

// ---- threefry2x32, JAX partitionable, key=(0,42) ----
__device__ __forceinline__ uint32_t rotl32(uint32_t x, int r) { return __funnelshift_l(x, x, r); }
#define TF_ROUND4(a, b, c, d)                       \
    x0 += x1; x1 = rotl32(x1, a); x1 ^= x0;         \
    x0 += x1; x1 = rotl32(x1, b); x1 ^= x0;         \
    x0 += x1; x1 = rotl32(x1, c); x1 ^= x0;         \
    x0 += x1; x1 = rotl32(x1, d); x1 ^= x0;
__device__ __forceinline__ uint32_t threefry_bits(uint32_t idx) {
    const uint32_t ks0 = 0u, ks1 = 42u;
    const uint32_t ks2 = 0x1BD11BDAu ^ ks0 ^ ks1;
    uint32_t x0 = 0u + ks0, x1 = idx + ks1;
    TF_ROUND4(13, 15, 26, 6)  x0 += ks1; x1 += ks2 + 1u;
    TF_ROUND4(17, 29, 16, 24) x0 += ks2; x1 += ks0 + 2u;
    TF_ROUND4(13, 15, 26, 6)  x0 += ks0; x1 += ks1 + 3u;
    TF_ROUND4(17, 29, 16, 24) x0 += ks1; x1 += ks2 + 4u;
    TF_ROUND4(13, 15, 26, 6)  x0 += ks2; x1 += ks0 + 5u;
    return x0 ^ x1;
}
__device__ __forceinline__ float dropscale(uint32_t idx, float v) {
    uint32_t bits = threefry_bits(idx);
    float u = __uint_as_float((bits >> 9) | 0x3f800000u) - 1.0f;
    return (u < 0.9f) ? v * (1.0f / 0.9f) : 0.0f;
}

// ---- stage 0 ----
__global__ __launch_bounds__(256) void bias_kernel(const float* __restrict__ C,
                                                   const float* __restrict__ Q,
                                                   const float* __restrict__ W) {
    int b = blockIdx.y;
    int m = blockIdx.x * 256 + threadIdx.x;
    const float* X; const float* wv; float* out;
    if (blockIdx.z == 0) { X = Q + (size_t)b * DD * MM; wv = W + b * 3 * DD;      out = g_sq + b * MM; }
    else                 { X = C + (size_t)b * DD * NN; wv = W + b * 3 * DD + DD; out = g_sc + b * NN; }
    __shared__ float ws[DD];
    if (threadIdx.x < DD) ws[threadIdx.x] = wv[threadIdx.x];
    __syncthreads();
    float acc = 0.0f;
#pragma unroll 8
    for (int d = 0; d < DD; d++) acc = fmaf(ws[d], X[(size_t)d * MM + m], acc);
    out[m] = acc;
}

__global__ __launch_bounds__(256) void split_cq_kernel(const float* __restrict__ C,
                                                       const float* __restrict__ Q) {
    size_t i = ((size_t)blockIdx.x * 256 + threadIdx.x) * 4;
    const float* src; __nv_bfloat16 *dh, *dl;
    if (blockIdx.y == 0) { src = C; dh = g_Chi; dl = g_Clo; }
    else                 { src = Q; dh = g_Qhi; dl = g_Qlo; }
    float4 v = *(const float4*)(src + i);
    *(uint2*)(dh + i) = make_uint2(packsplit_hi(v.x, v.y), packsplit_hi(v.z, v.w));
    *(uint2*)(dl + i) = make_uint2(packsplit_lo(v.x, v.y), packsplit_lo(v.z, v.w));
}

// ---- stage 1: S + fused stats (scalar f32x2, proven) ----
__global__ __launch_bounds__(256, 2) void gemm1_kernel(const float* __restrict__ C,
                                                       const float* __restrict__ Q,
                                                       const float* __restrict__ W) {
    int b = blockIdx.z, n0 = blockIdx.y * 128, m0 = blockIdx.x * 128;
    const float* Cb = C + (size_t)b * DD * NN;
    const float* Qb = Q + (size_t)b * DD * MM;
    const float* Wm = W + b * 3 * DD + 2 * DD;
    __shared__ float As[KC][128];
    __shared__ float Bs[KC][128];
    __shared__ float wm[DD];
    __shared__ float red[16][128];
    __shared__ float cmx[128];
    int tid = threadIdx.x, tx = tid & 15, ty = tid >> 4;
    if (tid < DD) wm[tid] = Wm[tid];
    __syncthreads();
    uint64_t acc2[8][4] = {};
    for (int k0 = 0; k0 < DD; k0 += KC) {
#pragma unroll
        for (int i = 0; i < 2; i++) {
            int li = tid + i * 256, kr = li >> 5, c4 = (li & 31) << 2;
            float w = wm[k0 + kr];
            float4 va = *(const float4*)(&Cb[(size_t)(k0 + kr) * NN + n0 + c4]);
            va.x *= w; va.y *= w; va.z *= w; va.w *= w;
            *(float4*)(&As[kr][c4]) = va;
            *(float4*)(&Bs[kr][c4]) = *(const float4*)(&Qb[(size_t)(k0 + kr) * MM + m0 + c4]);
        }
        __syncthreads();
#pragma unroll
        for (int kk = 0; kk < KC; kk++) {
            float a[8];
            *(float4*)(a)     = *(const float4*)(&As[kk][ty * 8]);
            *(float4*)(a + 4) = *(const float4*)(&As[kk][ty * 8 + 4]);
            ulonglong2 p0 = *(const ulonglong2*)(&Bs[kk][tx * 8]);
            ulonglong2 p1 = *(const ulonglong2*)(&Bs[kk][tx * 8 + 4]);
            uint64_t b2[4] = {p0.x, p0.y, p1.x, p1.y};
#pragma unroll
            for (int i = 0; i < 8; i++) {
                uint64_t a2 = pk2(a[i], a[i]);
#pragma unroll
                for (int j = 0; j < 4; j++) fma2(acc2[i][j], a2, b2[j]);
            }
        }
        __syncthreads();
    }
    float vals[8][8], sqv[8];
#pragma unroll
    for (int j = 0; j < 8; j++) sqv[j] = g_sq[b * MM + m0 + tx * 8 + j];
#pragma unroll
    for (int i = 0; i < 8; i++) {
        float sv = g_sc[b * NN + n0 + ty * 8 + i];
#pragma unroll
        for (int j = 0; j < 4; j++) {
            float2 f = upk2(acc2[i][j]);
            vals[i][j * 2] = f.x + sv + sqv[j * 2];
            vals[i][j * 2 + 1] = f.y + sv + sqv[j * 2 + 1];
        }
    }
    int tile_m = m0 >> 7, tile_n = n0 >> 7;
#pragma unroll
    for (int i = 0; i < 8; i++) {
        float mx = vals[i][0];
#pragma unroll
        for (int j = 1; j < 8; j++) mx = fmaxf(mx, vals[i][j]);
#pragma unroll
        for (int d = 1; d < 16; d <<= 1) mx = fmaxf(mx, __shfl_xor_sync(0xffffffffu, mx, d));
        float s = 0.0f;
#pragma unroll
        for (int j = 0; j < 8; j++) s += __expf(vals[i][j] - mx);
#pragma unroll
        for (int d = 1; d < 16; d <<= 1) s += __shfl_xor_sync(0xffffffffu, s, d);
        if (tx == 0) g_rowp[((size_t)(b * 16 + tile_m)) * NN + n0 + ty * 8 + i] = make_float2(mx, s);
    }
    {
        float lm[8];
#pragma unroll
        for (int j = 0; j < 8; j++) {
            float m = vals[0][j];
#pragma unroll
            for (int i = 1; i < 8; i++) m = fmaxf(m, vals[i][j]);
            lm[j] = m;
        }
        *(float4*)(&red[ty][tx * 8]) = *(float4*)(lm);
        *(float4*)(&red[ty][tx * 8 + 4]) = *(float4*)(lm + 4);
        __syncthreads();
        if (tid < 128) {
            float m = red[0][tid];
#pragma unroll
            for (int t = 1; t < 16; t++) m = fmaxf(m, red[t][tid]);
            cmx[tid] = m;
        }
        __syncthreads();
        float ls[8];
#pragma unroll
        for (int j = 0; j < 8; j++) {
            float cm = cmx[tx * 8 + j], s = 0.0f;
#pragma unroll
            for (int i = 0; i < 8; i++) s += __expf(vals[i][j] - cm);
            ls[j] = s;
        }
        __syncthreads();
        *(float4*)(&red[ty][tx * 8]) = *(float4*)(ls);
        *(float4*)(&red[ty][tx * 8 + 4]) = *(float4*)(ls + 4);
        __syncthreads();
        if (tid < 128) {
            float s = red[0][tid];
#pragma unroll
            for (int t = 1; t < 16; t++) s += red[t][tid];
            g_colp[((size_t)(b * 16 + tile_n)) * MM + m0 + tid] = make_float2(cmx[tid], s);
        }
    }
    float* Sb = g_S + (size_t)b * NN * MM;
#pragma unroll
    for (int i = 0; i < 8; i++) {
        float* dst = Sb + (size_t)(n0 + ty * 8 + i) * MM + m0 + tx * 8;
        *(float4*)dst = *(float4*)(&vals[i][0]);
        *(float4*)(dst + 4) = *(float4*)(&vals[i][4]);
    }
}

// ---- stage 2: combines ----
__global__ __launch_bounds__(256) void rowcombine_kernel() {
    int idx = blockIdx.x * 256 + threadIdx.x;
    int b = idx >> 11, n = idx & (NN - 1);
    const float2* p = g_rowp + (size_t)(b * 16) * NN + n;
    float2 f = p[0]; float mx = f.x, s = f.y;
#pragma unroll
    for (int t = 1; t < 16; t++) {
        float2 g = p[(size_t)t * NN];
        float nm = fmaxf(mx, g.x);
        s = s * __expf(mx - nm) + g.y * __expf(g.x - nm); mx = nm;
    }
    g_L1[idx] = mx + logf(s);
}
__global__ __launch_bounds__(256) void colcombine_kernel() {
    int idx = blockIdx.x * 256 + threadIdx.x;
    int b = idx >> 11, m = idx & (MM - 1);
    const float2* p = g_colp + (size_t)(b * 16) * MM + m;
    float2 f = p[0]; float mx = f.x, s = f.y;
#pragma unroll
    for (int t = 1; t < 16; t++) {
        float2 g = p[(size_t)t * MM];
        float nm = fmaxf(mx, g.x);
        s = s * __expf(mx - nm) + g.y * __expf(g.x - nm); mx = nm;
    }
    g_L2[idx] = mx + logf(s);
}

// ---- stage 3: CB = C * E2 via HMMA (M=d(128), N=m(128), K=n(2048)) ----
// smem: l2s[128]f, then 4 tiles [128 rows][16 u32 words], XOR-swizzled
#define T_WORDS 2048
__global__ __launch_bounds__(256) void cb_mma() {
    extern __shared__ char smc[];
    float* l2s = (float*)smc;
    uint32_t* AH = (uint32_t*)(smc + 512);
    uint32_t* AL = AH + T_WORDS;
    uint32_t* EH = AL + T_WORDS;
    uint32_t* EL = EH + T_WORDS;
    int tid = threadIdx.x, lane = tid & 31, wid = tid >> 5;
    int b = blockIdx.y, m0 = blockIdx.x * 128;
    if (tid < 128) l2s[tid] = g_L2[b * MM + m0 + tid];
    const float* Sb = g_S + (size_t)b * NN * MM;
    const __nv_bfloat16* Ch = g_Chi + (size_t)b * DD * NN;
    const __nv_bfloat16* Cl = g_Clo + (size_t)b * DD * NN;
    int wm = (wid & 1) * 64, wn = (wid >> 1) * 32;
    int g = lane >> 2, t4 = lane & 3;
    float acc[4][4][4] = {};
    int ar = tid >> 1, ac = (tid & 1) * 2, asw = (ar >> 1) & 3;
    int kp = tid & 15, mb = tid >> 4;
    __syncthreads();
    for (int c = 0; c < NN / KB; c++) {
        int n0 = c * KB;
        {   // A fill: C rows d=ar, 2 chunks of 8 bf16
            const uint4* ph = (const uint4*)(Ch + (size_t)ar * NN + n0);
            const uint4* pl = (const uint4*)(Cl + (size_t)ar * NN + n0);
            ((uint4*)AH)[ar * 4 + (ac ^ asw)]       = ph[ac];
            ((uint4*)AH)[ar * 4 + ((ac + 1) ^ asw)] = ph[ac + 1];
            ((uint4*)AL)[ar * 4 + (ac ^ asw)]       = pl[ac];
            ((uint4*)AL)[ar * 4 + ((ac + 1) ^ asw)] = pl[ac + 1];
        }
        {   // E2^T fill: E[m][k=n], k pair = 2kp,2kp+1; m = mb*8+i
            const float* s0 = Sb + (size_t)(n0 + 2 * kp) * MM + m0 + mb * 8;
            const float* s1 = s0 + MM;
            float4 x0 = *(const float4*)s0, x1 = *(const float4*)(s0 + 4);
            float4 y0 = *(const float4*)s1, y1 = *(const float4*)(s1 + 4);
            float xs[8] = {x0.x, x0.y, x0.z, x0.w, x1.x, x1.y, x1.z, x1.w};
            float ys[8] = {y0.x, y0.y, y0.z, y0.w, y1.x, y1.y, y1.z, y1.w};
#pragma unroll
            for (int i = 0; i < 8; i++) {
                int m = mb * 8 + i;
                float L = l2s[m];
                float e0 = fexp(xs[i] - L), e1 = fexp(ys[i] - L);
                int w = m * 16 + (kp ^ (((m >> 1) & 3) << 2));
                EH[w] = packsplit_hi(e0, e1);
                EL[w] = packsplit_lo(e0, e1);
            }
        }
        __syncthreads();
#pragma unroll
        for (int ks = 0; ks < 2; ks++) {
            uint32_t bh[4][2], bl[4][2];
#pragma unroll
            for (int nt = 0; nt < 4; nt++) {
                int j = wn + nt * 8 + g;
                int sj = ((j >> 1) & 3) << 2;
                int w0 = j * 16 + ((ks * 8 + t4) ^ sj);
                int w1 = j * 16 + ((ks * 8 + 4 + t4) ^ sj);
                bh[nt][0] = EH[w0]; bh[nt][1] = EH[w1];
                bl[nt][0] = EL[w0]; bl[nt][1] = EL[w1];
            }
#pragma unroll
            for (int mt = 0; mt < 4; mt++) {
                int m = wm + mt * 16 + g;
                int sw = ((m >> 1) & 3) << 2;
                int w0 = (ks * 8 + t4) ^ sw, w1 = (ks * 8 + 4 + t4) ^ sw;
                uint32_t ah[4] = {AH[m * 16 + w0], AH[(m + 8) * 16 + w0],
                                  AH[m * 16 + w1], AH[(m + 8) * 16 + w1]};
                uint32_t al[4] = {AL[m * 16 + w0], AL[(m + 8) * 16 + w0],
                                  AL[m * 16 + w1], AL[(m + 8) * 16 + w1]};
#pragma unroll
                for (int nt = 0; nt < 4; nt++) {
                    mma16816(acc[mt][nt], ah, bh[nt]);
                    mma16816(acc[mt][nt], ah, bl[nt]);
                    mma16816(acc[mt][nt], al, bh[nt]);
                }
            }
        }
        __syncthreads();
    }
    // writeout -> CB hi/lo bf16
#pragma unroll
    for (int mt = 0; mt < 4; mt++) {
#pragma unroll
        for (int nt = 0; nt < 4; nt++) {
            float* cfr = acc[mt][nt];
            int d0 = wm + mt * 16 + g;
            int col = m0 + wn + nt * 8 + t4 * 2;
            size_t o0 = (size_t)(b * DD + d0) * MM + col;
            size_t o1 = (size_t)(b * DD + d0 + 8) * MM + col;
            *(uint32_t*)(g_CBhi + o0) = packsplit_hi(cfr[0], cfr[1]);
            *(uint32_t*)(g_CBlo + o0) = packsplit_lo(cfr[0], cfr[1]);
            *(uint32_t*)(g_CBhi + o1) = packsplit_hi(cfr[2], cfr[3]);
            *(uint32_t*)(g_CBlo + o1) = packsplit_lo(cfr[2], cfr[3]);
        }
    }
}

// ---- stage 4: A (z=0) / Bt (z=1): out[r][n] = sum_m X[r][m]*E1[n][m] ----
__global__ __launch_bounds__(256) void ab_mma() {
    extern __shared__ char smc[];
    float* l1s = (float*)smc;
    uint32_t* AH = (uint32_t*)(smc + 512);
    uint32_t* AL = AH + T_WORDS;
    uint32_t* EH = AL + T_WORDS;
    uint32_t* EL = EH + T_WORDS;
    int tid = threadIdx.x, lane = tid & 31, wid = tid >> 5;
    int b = blockIdx.y, n0 = blockIdx.x * 128, z = blockIdx.z;
    if (tid < 128) l1s[tid] = g_L1[b * NN + n0 + tid];
    const float* Sb = g_S + (size_t)b * NN * MM;
    const __nv_bfloat16* Xh = (z ? g_CBhi : g_Qhi) + (size_t)b * DD * MM;
    const __nv_bfloat16* Xl = (z ? g_CBlo : g_Qlo) + (size_t)b * DD * MM;
    float* Out = (z ? g_Bt : g_A) + (size_t)b * DD * NN;
    int wm = (wid & 1) * 64, wn = (wid >> 1) * 32;
    int g = lane >> 2, t4 = lane & 3;
    float acc[4][4][4] = {};
    int ar = tid >> 1, ac = (tid & 1) * 2, asw = (ar >> 1) & 3;
    int nr = tid >> 1, half = tid & 1;
    __syncthreads();
    for (int c = 0; c < MM / KB; c++) {
        int mc0 = c * KB;
        {   // A fill: X rows r=ar
            const uint4* ph = (const uint4*)(Xh + (size_t)ar * MM + mc0);
            const uint4* pl = (const uint4*)(Xl + (size_t)ar * MM + mc0);
            ((uint4*)AH)[ar * 4 + (ac ^ asw)]       = ph[ac];
            ((uint4*)AH)[ar * 4 + ((ac + 1) ^ asw)] = ph[ac + 1];
            ((uint4*)AL)[ar * 4 + (ac ^ asw)]       = pl[ac];
            ((uint4*)AL)[ar * 4 + ((ac + 1) ^ asw)] = pl[ac + 1];
        }
        {   // E1 fill: E[n][k=m], row n = nr, 16 m at half*16
            const float* sp = Sb + (size_t)(n0 + nr) * MM + mc0 + half * 16;
            float4 v0 = *(const float4*)sp, v1 = *(const float4*)(sp + 4);
            float4 v2 = *(const float4*)(sp + 8), v3 = *(const float4*)(sp + 12);
            float vs[16] = {v0.x, v0.y, v0.z, v0.w, v1.x, v1.y, v1.z, v1.w,
                            v2.x, v2.y, v2.z, v2.w, v3.x, v3.y, v3.z, v3.w};
            float L = l1s[nr];
            int sn = ((nr >> 1) & 3) << 2;
#pragma unroll
            for (int q = 0; q < 8; q++) {
                float e0 = fexp(vs[2 * q] - L), e1 = fexp(vs[2 * q + 1] - L);
                int w = nr * 16 + ((half * 8 + q) ^ sn);
                EH[w] = packsplit_hi(e0, e1);
                EL[w] = packsplit_lo(e0, e1);
            }
        }
        __syncthreads();
#pragma unroll
        for (int ks = 0; ks < 2; ks++) {
            uint32_t bh[4][2], bl[4][2];
#pragma unroll
            for (int nt = 0; nt < 4; nt++) {
                int j = wn + nt * 8 + g;
                int sj = ((j >> 1) & 3) << 2;
                int w0 = j * 16 + ((ks * 8 + t4) ^ sj);
                int w1 = j * 16 + ((ks * 8 + 4 + t4) ^ sj);
                bh[nt][0] = EH[w0]; bh[nt][1] = EH[w1];
                bl[nt][0] = EL[w0]; bl[nt][1] = EL[w1];
            }
#pragma unroll
            for (int mt = 0; mt < 4; mt++) {
                int m = wm + mt * 16 + g;
                int sw = ((m >> 1) & 3) << 2;
                int w0 = (ks * 8 + t4) ^ sw, w1 = (ks * 8 + 4 + t4) ^ sw;
                uint32_t ah[4] = {AH[m * 16 + w0], AH[(m + 8) * 16 + w0],
                                  AH[m * 16 + w1], AH[(m + 8) * 16 + w1]};
                uint32_t al[4] = {AL[m * 16 + w0], AL[(m + 8) * 16 + w0],
                                  AL[m * 16 + w1], AL[(m + 8) * 16 + w1]};
#pragma unroll
                for (int nt = 0; nt < 4; nt++) {
                    mma16816(acc[mt][nt], ah, bh[nt]);
                    mma16816(acc[mt][nt], ah, bl[nt]);
                    mma16816(acc[mt][nt], al, bh[nt]);
                }
            }
        }
        __syncthreads();
    }
#pragma unroll
    for (int mt = 0; mt < 4; mt++) {
#pragma unroll
        for (int nt = 0; nt < 4; nt++) {
            float* cfr = acc[mt][nt];
            int r0 = wm + mt * 16 + g;
            int col = n0 + wn + nt * 8 + t4 * 2;
            *(float2*)(Out + (size_t)r0 * NN + col)       = make_float2(cfr[0], cfr[1]);
            *(float2*)(Out + (size_t)(r0 + 8) * NN + col) = make_float2(cfr[2], cfr[3]);
        }
    }
}

// ---- stage 5: concat + dropout ----
__device__ __forceinline__ void write_drop4(float* p, size_t idx, float4 v) {
    float4 o;
    o.x = dropscale((uint32_t)(idx + 0), v.x);
    o.y = dropscale((uint32_t)(idx + 1), v.y);
    o.z = dropscale((uint32_t)(idx + 2), v.z);
    o.w = dropscale((uint32_t)(idx + 3), v.w);
    *(float4*)p = o;
}
__global__ __launch_bounds__(256) void epilogue_kernel(const float* __restrict__ C,
                                                       float* __restrict__ out) {
    unsigned gi = blockIdx.x * 256u + threadIdx.x;
    unsigned t = gi & 511u, bd = gi >> 9, d = bd & 127u, b = bd >> 7, n = t * 4u;
    size_t src = ((size_t)(b * DD + d)) * NN + n;
    float4 c = *(const float4*)(C + src);
    float4 a = *(const float4*)(g_A + src);
    float4 bt = *(const float4*)(g_Bt + src);
    float4 ca = make_float4(c.x * a.x, c.y * a.y, c.z * a.z, c.w * a.w);
    float4 cbt = make_float4(c.x * bt.x, c.y * bt.y, c.z * bt.z, c.w * bt.w);
    size_t o0 = ((size_t)b * 4 * DD + d) * NN + n;
    const size_t st = (size_t)DD * NN;
    write_drop4(out + o0, o0, c);
    write_drop4(out + o0 + st, o0 + st, a);
    write_drop4(out + o0 + 2 * st, o0 + 2 * st, ca);
    write_drop4(out + o0 + 3 * st, o0 + 3 * st, cbt);
}

// ---- launch ----
#define MMA_SMEM (512 + 4 * 8192)
extern "C" void kernel_launch(void* const* d_in, const int* in_sizes, int n_in,
                              void* d_out, int out_size) {
    const float* C = (const float*)d_in[0];
    const float* Q = (const float*)d_in[1];
    const float* W = (const float*)d_in[2];
    float* out = (float*)d_out;
    bias_kernel<<<dim3(MM / 256, BB, 2), 256>>>(C, Q, W);
    split_cq_kernel<<<dim3((BB * DD * NN / 4) / 256, 2), 256>>>(C, Q);
    gemm1_kernel<<<dim3(MM / 128, NN / 128, BB), 256>>>(C, Q, W);
    rowcombine_kernel<<<dim3((BB * NN) / 256), 256>>>();
    colcombine_kernel<<<dim3((BB * MM) / 256), 256>>>();
    cb_mma<<<dim3(MM / 128, BB), 256, MMA_SMEM>>>();
    ab_mma<<<dim3(NN / 128, BB, 2), 256, MMA_SMEM>>>();
    epilogue_kernel<<<dim3((BB * DD * NN / 4) / 256), 256>>>(C, out);
}

// round 9
// speedup vs baseline: 1.6924x; 1.1223x over previous
#include <cuda_runtime.h>
#include <cuda_bf16.h>
#include <cstdint>
#include <cstddef>

#define BB 24
#define DD 128
#define NN 2048
#define MM 2048
#define KB 32
#define T_WORDS 2048

__device__ float g_S [(size_t)BB * NN * MM];
__device__ float g_A [(size_t)BB * DD * NN];
__device__ float g_Bt[(size_t)BB * DD * NN];
__device__ float g_L1[BB * NN];
__device__ float g_L2[BB * MM];
__device__ float g_sq[BB * MM];
__device__ float g_sc[BB * NN];
__device__ float2 g_rowp[(size_t)BB * 16 * NN];
__device__ float2 g_colp[(size_t)BB * 16 * MM];
__device__ __nv_bfloat16 g_Chi[(size_t)BB * DD * NN];
__device__ __nv_bfloat16 g_Clo[(size_t)BB * DD * NN];
__device__ __nv_bfloat16 g_Qhi[(size_t)BB * DD * MM];
__device__ __nv_bfloat16 g_Qlo[(size_t)BB * DD * MM];
__device__ __nv_bfloat16 g_CBhi[(size_t)BB * DD * MM];
__device__ __nv_bfloat16 g_CBlo[(size_t)BB * DD * MM];
__device__ __nv_bfloat16 g_CThi[(size_t)BB * NN * DD];
__device__ __nv_bfloat16 g_CTlo[(size_t)BB * NN * DD];
__device__ __nv_bfloat16 g_QWhi[(size_t)BB * MM * DD];
__device__ __nv_bfloat16 g_QWlo[(size_t)BB * MM * DD];

// ---- warp mma (baseline sm_80+ HMMA) ----
__device__ __forceinline__ void mma16816(float* c, const uint32_t* a, const uint32_t* b) {
    asm volatile("mma.sync.aligned.m16n8k16.row.col.f32.bf16.bf16.f32 "
                 "{%0,%1,%2,%3},{%4,%5,%6,%7},{%8,%9},{%0,%1,%2,%3};"
                 : "+f"(c[0]), "+f"(c[1]), "+f"(c[2]), "+f"(c[3])
                 : "r"(a[0]), "r"(a[1]), "r"(a[2]), "r"(a[3]), "r"(b[0]), "r"(b[1]));
}

__device__ __forceinline__ void splitf(float x, uint16_t& h, uint16_t& l) {
    __nv_bfloat16 bh = __float2bfloat16_rn(x);
    float r = x - __bfloat162float(bh);
    __nv_bfloat16 bl = __float2bfloat16_rn(r);
    h = __bfloat16_as_ushort(bh); l = __bfloat16_as_ushort(bl);
}
__device__ __forceinline__ uint32_t packsplit_hi(float a, float b) {
    uint16_t h0, l0, h1, l1; splitf(a, h0, l0); splitf(b, h1, l1);
    return (uint32_t)h0 | ((uint32_t)h1 << 16);
}
__device__ __forceinline__ uint32_t packsplit_lo(float a, float b) {
    uint16_t h0, l0, h1, l1; splitf(a, h0, l0); splitf(b, h1, l1);
    return (uint32_t)l0 | ((uint32_t)l1 << 16);
}
// fast exp on FMA pipe (rel err ~2.4e-6)
__device__ __forceinline__ float fexp(float x) {
    float t = fmaxf(x * 1.4426950408889634f, -126.0f);
    float kf = t + 12582912.0f;
    float fi = kf - 12582912.0f;
    float f = t - fi;
    float p = 1.3333558146e-3f;
    p = fmaf(p, f, 9.6181291076e-3f);
    p = fmaf(p, f, 5.5504108665e-2f);
    p = fmaf(p, f, 2.4022650696e-1f);
    p = fmaf(p, f, 6.9314718056e-1f);
    p = fmaf(p, f, 1.0f);
    return __int_as_float(__float_as_int(p) + (((int)fi) << 23));
}

// ---- threefry2x32, JAX partitionable, key=(0,42) ----
__device__ __forceinline__ uint32_t rotl32(uint32_t x, int r) { return __funnelshift_l(x, x, r); }
#define TF_ROUND4(a, b, c, d)                       \
    x0 += x1; x1 = rotl32(x1, a); x1 ^= x0;         \
    x0 += x1; x1 = rotl32(x1, b); x1 ^= x0;         \
    x0 += x1; x1 = rotl32(x1, c); x1 ^= x0;         \
    x0 += x1; x1 = rotl32(x1, d); x1 ^= x0;
__device__ __forceinline__ uint32_t threefry_bits(uint32_t idx) {
    const uint32_t ks0 = 0u, ks1 = 42u;
    const uint32_t ks2 = 0x1BD11BDAu ^ ks0 ^ ks1;
    uint32_t x0 = 0u + ks0, x1 = idx + ks1;
    TF_ROUND4(13, 15, 26, 6)  x0 += ks1; x1 += ks2 + 1u;
    TF_ROUND4(17, 29, 16, 24) x0 += ks2; x1 += ks0 + 2u;
    TF_ROUND4(13, 15, 26, 6)  x0 += ks0; x1 += ks1 + 3u;
    TF_ROUND4(17, 29, 16, 24) x0 += ks1; x1 += ks2 + 4u;
    TF_ROUND4(13, 15, 26, 6)  x0 += ks2; x1 += ks0 + 5u;
    return x0 ^ x1;
}
__device__ __forceinline__ float dropscale(uint32_t idx, float v) {
    uint32_t bits = threefry_bits(idx);
    float u = __uint_as_float((bits >> 9) | 0x3f800000u) - 1.0f;
    return (u < 0.9f) ? v * (1.0f / 0.9f) : 0.0f;
}

// ---- stage 0: biases ----
__global__ __launch_bounds__(256) void bias_kernel(const float* __restrict__ C,
                                                   const float* __restrict__ Q,
                                                   const float* __restrict__ W) {
    int b = blockIdx.y;
    int m = blockIdx.x * 256 + threadIdx.x;
    const float* X; const float* wv; float* out;
    if (blockIdx.z == 0) { X = Q + (size_t)b * DD * MM; wv = W + b * 3 * DD;      out = g_sq + b * MM; }
    else                 { X = C + (size_t)b * DD * NN; wv = W + b * 3 * DD + DD; out = g_sc + b * NN; }
    __shared__ float ws[DD];
    if (threadIdx.x < DD) ws[threadIdx.x] = wv[threadIdx.x];
    __syncthreads();
    float acc = 0.0f;
#pragma unroll 8
    for (int d = 0; d < DD; d++) acc = fmaf(ws[d], X[(size_t)d * MM + m], acc);
    out[m] = acc;
}

// ---- stage 0b: split C,Q in [d][*] layout (consumers) ----
__global__ __launch_bounds__(256) void split_cq_kernel(const float* __restrict__ C,
                                                       const float* __restrict__ Q) {
    size_t i = ((size_t)blockIdx.x * 256 + threadIdx.x) * 4;
    const float* src; __nv_bfloat16 *dh, *dl;
    if (blockIdx.y == 0) { src = C; dh = g_Chi; dl = g_Clo; }
    else                 { src = Q; dh = g_Qhi; dl = g_Qlo; }
    float4 v = *(const float4*)(src + i);
    *(uint2*)(dh + i) = make_uint2(packsplit_hi(v.x, v.y), packsplit_hi(v.z, v.w));
    *(uint2*)(dl + i) = make_uint2(packsplit_lo(v.x, v.y), packsplit_lo(v.z, v.w));
}

// ---- stage 0c: transpose-split for s_mma: CT[n][d], QW[m][d] (Wm folded) ----
__global__ __launch_bounds__(256) void tsplit_kernel(const float* __restrict__ C,
                                                     const float* __restrict__ Q,
                                                     const float* __restrict__ W) {
    __shared__ float ts[32][33];
    __shared__ float wsc[32];
    int z = blockIdx.z, b = z >> 1, isQ = z & 1;
    int n0 = blockIdx.x * 32, d0 = blockIdx.y * 32;
    const float* X = (isQ ? Q : C) + (size_t)b * DD * NN;
    int t = threadIdx.x, nl = t & 31, dr = t >> 5;
    if (t < 32) wsc[t] = isQ ? W[b * 3 * DD + 2 * DD + d0 + t] : 1.0f;
#pragma unroll
    for (int k = 0; k < 4; k++)
        ts[dr + k * 8][nl] = X[(size_t)(d0 + dr + k * 8) * NN + n0 + nl];
    __syncthreads();
    int nr = t >> 3, dg = (t & 7) * 4;
    __nv_bfloat16* dh = (isQ ? g_QWhi : g_CThi) + ((size_t)b * NN + n0 + nr) * DD + d0 + dg;
    __nv_bfloat16* dl = (isQ ? g_QWlo : g_CTlo) + ((size_t)b * NN + n0 + nr) * DD + d0 + dg;
    float v0 = ts[dg][nr] * wsc[dg],     v1 = ts[dg + 1][nr] * wsc[dg + 1];
    float v2 = ts[dg + 2][nr] * wsc[dg + 2], v3 = ts[dg + 3][nr] * wsc[dg + 3];
    *(uint2*)dh = make_uint2(packsplit_hi(v0, v1), packsplit_hi(v2, v3));
    *(uint2*)dl = make_uint2(packsplit_lo(v0, v1), packsplit_lo(v2, v3));
}

// ---- stage 1: S = CT * QW^T via HMMA + biases + fused stats ----
#define G1_SMEM (1024 + 4 * 8192)
__global__ __launch_bounds__(256) void s_mma() {
    extern __shared__ char smc[];
    float* sc_s = (float*)smc;
    float* sq_s = (float*)(smc + 512);
    uint32_t* AH = (uint32_t*)(smc + 1024);
    uint32_t* AL = AH + T_WORDS;
    uint32_t* BH = AL + T_WORDS;
    uint32_t* BL = BH + T_WORDS;
    float* st  = (float*)(smc + 1024);   // alias tiles after mainloop
    float* rm4 = st;                      // [4][128]
    float* rfin = st + 512;               // [128]
    float* rs4 = st + 640;                // [4][128]
    float* cm2 = st + 1152;               // [2][128]
    float* cfin = st + 1408;              // [128]
    float* cs2 = st + 1536;               // [2][128]
    int tid = threadIdx.x, lane = tid & 31, wid = tid >> 5;
    int b = blockIdx.z, n0 = blockIdx.y * 128, m0 = blockIdx.x * 128;
    if (tid < 128) { sc_s[tid] = g_sc[b * NN + n0 + tid]; sq_s[tid] = g_sq[b * MM + m0 + tid]; }
    const __nv_bfloat16* Ahg = g_CThi + ((size_t)b * NN + n0) * DD;
    const __nv_bfloat16* Alg = g_CTlo + ((size_t)b * NN + n0) * DD;
    const __nv_bfloat16* Bhg = g_QWhi + ((size_t)b * MM + m0) * DD;
    const __nv_bfloat16* Blg = g_QWlo + ((size_t)b * MM + m0) * DD;
    int wm = (wid & 1) * 64, wn = (wid >> 1) * 32;
    int g = lane >> 2, t4 = lane & 3;
    float acc[4][4][4] = {};
    int ar = tid >> 1, ac = (tid & 1) * 2, asw = (ar >> 1) & 3;
    __syncthreads();
    for (int c = 0; c < 4; c++) {
        const uint4* pah = (const uint4*)(Ahg + (size_t)ar * DD + c * 32);
        const uint4* pal = (const uint4*)(Alg + (size_t)ar * DD + c * 32);
        const uint4* pbh = (const uint4*)(Bhg + (size_t)ar * DD + c * 32);
        const uint4* pbl = (const uint4*)(Blg + (size_t)ar * DD + c * 32);
        ((uint4*)AH)[ar * 4 + (ac ^ asw)]       = pah[ac];
        ((uint4*)AH)[ar * 4 + ((ac + 1) ^ asw)] = pah[ac + 1];
        ((uint4*)AL)[ar * 4 + (ac ^ asw)]       = pal[ac];
        ((uint4*)AL)[ar * 4 + ((ac + 1) ^ asw)] = pal[ac + 1];
        ((uint4*)BH)[ar * 4 + (ac ^ asw)]       = pbh[ac];
        ((uint4*)BH)[ar * 4 + ((ac + 1) ^ asw)] = pbh[ac + 1];
        ((uint4*)BL)[ar * 4 + (ac ^ asw)]       = pbl[ac];
        ((uint4*)BL)[ar * 4 + ((ac + 1) ^ asw)] = pbl[ac + 1];
        __syncthreads();
#pragma unroll
        for (int ks = 0; ks < 2; ks++) {
            uint32_t bh[4][2], bl[4][2];
#pragma unroll
            for (int nt = 0; nt < 4; nt++) {
                int j = wn + nt * 8 + g;
                int sj = ((j >> 1) & 3) << 2;
                int w0 = j * 16 + ((ks * 8 + t4) ^ sj);
                int w1 = j * 16 + ((ks * 8 + 4 + t4) ^ sj);
                bh[nt][0] = BH[w0]; bh[nt][1] = BH[w1];
                bl[nt][0] = BL[w0]; bl[nt][1] = BL[w1];
            }
#pragma unroll
            for (int mt = 0; mt < 4; mt++) {
                int m = wm + mt * 16 + g;
                int sw = ((m >> 1) & 3) << 2;
                int w0 = (ks * 8 + t4) ^ sw, w1 = (ks * 8 + 4 + t4) ^ sw;
                uint32_t ah[4] = {AH[m * 16 + w0], AH[(m + 8) * 16 + w0],
                                  AH[m * 16 + w1], AH[(m + 8) * 16 + w1]};
                uint32_t al[4] = {AL[m * 16 + w0], AL[(m + 8) * 16 + w0],
                                  AL[m * 16 + w1], AL[(m + 8) * 16 + w1]};
#pragma unroll
                for (int nt = 0; nt < 4; nt++) {
                    mma16816(acc[mt][nt], ah, bh[nt]);
                    mma16816(acc[mt][nt], ah, bl[nt]);
                    mma16816(acc[mt][nt], al, bh[nt]);
                }
            }
        }
        __syncthreads();
    }
    // biases + store S
    float* Sb = g_S + (size_t)b * NN * MM;
#pragma unroll
    for (int mt = 0; mt < 4; mt++) {
#pragma unroll
        for (int nt = 0; nt < 4; nt++) {
            int r0 = wm + mt * 16 + g, c0 = wn + nt * 8 + t4 * 2;
            acc[mt][nt][0] += sc_s[r0] + sq_s[c0];
            acc[mt][nt][1] += sc_s[r0] + sq_s[c0 + 1];
            acc[mt][nt][2] += sc_s[r0 + 8] + sq_s[c0];
            acc[mt][nt][3] += sc_s[r0 + 8] + sq_s[c0 + 1];
            *(float2*)(Sb + (size_t)(n0 + r0) * MM + m0 + c0)     = make_float2(acc[mt][nt][0], acc[mt][nt][1]);
            *(float2*)(Sb + (size_t)(n0 + r0 + 8) * MM + m0 + c0) = make_float2(acc[mt][nt][2], acc[mt][nt][3]);
        }
    }
    // row stats: max then sumexp over cols (m)
#pragma unroll
    for (int mt = 0; mt < 4; mt++) {
#pragma unroll
        for (int h = 0; h < 2; h++) {
            float m = acc[mt][0][h * 2];
#pragma unroll
            for (int nt = 0; nt < 4; nt++) {
                m = fmaxf(m, acc[mt][nt][h * 2]);
                m = fmaxf(m, acc[mt][nt][h * 2 + 1]);
            }
            m = fmaxf(m, __shfl_xor_sync(0xffffffffu, m, 1));
            m = fmaxf(m, __shfl_xor_sync(0xffffffffu, m, 2));
            if (t4 == 0) rm4[(wid >> 1) * 128 + wm + mt * 16 + g + 8 * h] = m;
        }
    }
    __syncthreads();
    if (tid < 128)
        rfin[tid] = fmaxf(fmaxf(rm4[tid], rm4[128 + tid]), fmaxf(rm4[256 + tid], rm4[384 + tid]));
    __syncthreads();
#pragma unroll
    for (int mt = 0; mt < 4; mt++) {
#pragma unroll
        for (int h = 0; h < 2; h++) {
            int r = wm + mt * 16 + g + 8 * h;
            float L = rfin[r], s = 0.0f;
#pragma unroll
            for (int nt = 0; nt < 4; nt++)
                s += fexp(acc[mt][nt][h * 2] - L) + fexp(acc[mt][nt][h * 2 + 1] - L);
            s += __shfl_xor_sync(0xffffffffu, s, 1);
            s += __shfl_xor_sync(0xffffffffu, s, 2);
            if (t4 == 0) rs4[(wid >> 1) * 128 + r] = s;
        }
    }
    __syncthreads();
    if (tid < 128)
        g_rowp[((size_t)(b * 16 + (m0 >> 7))) * NN + n0 + tid] =
            make_float2(rfin[tid], rs4[tid] + rs4[128 + tid] + rs4[256 + tid] + rs4[384 + tid]);
    // col stats: max then sumexp over rows (n)
#pragma unroll
    for (int nt = 0; nt < 4; nt++) {
#pragma unroll
        for (int e = 0; e < 2; e++) {
            float m = acc[0][nt][e];
#pragma unroll
            for (int mt = 0; mt < 4; mt++) {
                m = fmaxf(m, acc[mt][nt][e]);
                m = fmaxf(m, acc[mt][nt][2 + e]);
            }
            m = fmaxf(m, __shfl_xor_sync(0xffffffffu, m, 4));
            m = fmaxf(m, __shfl_xor_sync(0xffffffffu, m, 8));
            m = fmaxf(m, __shfl_xor_sync(0xffffffffu, m, 16));
            if (g == 0) cm2[(wid & 1) * 128 + wn + nt * 8 + t4 * 2 + e] = m;
        }
    }
    __syncthreads();
    if (tid < 128) cfin[tid] = fmaxf(cm2[tid], cm2[128 + tid]);
    __syncthreads();
#pragma unroll
    for (int nt = 0; nt < 4; nt++) {
#pragma unroll
        for (int e = 0; e < 2; e++) {
            int c = wn + nt * 8 + t4 * 2 + e;
            float L = cfin[c], s = 0.0f;
#pragma unroll
            for (int mt = 0; mt < 4; mt++)
                s += fexp(acc[mt][nt][e] - L) + fexp(acc[mt][nt][2 + e] - L);
            s += __shfl_xor_sync(0xffffffffu, s, 4);
            s += __shfl_xor_sync(0xffffffffu, s, 8);
            s += __shfl_xor_sync(0xffffffffu, s, 16);
            if (g == 0) cs2[(wid & 1) * 128 + c] = s;
        }
    }
    __syncthreads();
    if (tid < 128)
        g_colp[((size_t)(b * 16 + (n0 >> 7))) * MM + m0 + tid] =
            make_float2(cfin[tid], cs2[tid] + cs2[128 + tid]);
}

// ---- stage 2: combines ----
__global__ __launch_bounds__(256) void rowcombine_kernel() {
    int idx = blockIdx.x * 256 + threadIdx.x;
    int b = idx >> 11, n = idx & (NN - 1);
    const float2* p = g_rowp + (size_t)(b * 16) * NN + n;
    float2 f = p[0]; float mx = f.x, s = f.y;
#pragma unroll
    for (int t = 1; t < 16; t++) {
        float2 g = p[(size_t)t * NN];
        float nm = fmaxf(mx, g.x);
        s = s * __expf(mx - nm) + g.y * __expf(g.x - nm); mx = nm;
    }
    g_L1[idx] = mx + logf(s);
}
__global__ __launch_bounds__(256) void colcombine_kernel() {
    int idx = blockIdx.x * 256 + threadIdx.x;
    int b = idx >> 11, m = idx & (MM - 1);
    const float2* p = g_colp + (size_t)(b * 16) * MM + m;
    float2 f = p[0]; float mx = f.x, s = f.y;
#pragma unroll
    for (int t = 1; t < 16; t++) {
        float2 g = p[(size_t)t * MM];
        float nm = fmaxf(mx, g.x);
        s = s * __expf(mx - nm) + g.y * __expf(g.x - nm); mx = nm;
    }
    g_L2[idx] = mx + logf(s);
}

// ---- stage 3: CB = C * E2 via HMMA ----
__global__ __launch_bounds__(256) void cb_mma() {
    extern __shared__ char smc[];
    float* l2s = (float*)smc;
    uint32_t* AH = (uint32_t*)(smc + 512);
    uint32_t* AL = AH + T_WORDS;
    uint32_t* EH = AL + T_WORDS;
    uint32_t* EL = EH + T_WORDS;
    int tid = threadIdx.x, lane = tid & 31, wid = tid >> 5;
    int b = blockIdx.y, m0 = blockIdx.x * 128;
    if (tid < 128) l2s[tid] = g_L2[b * MM + m0 + tid];
    const float* Sb = g_S + (size_t)b * NN * MM;
    const __nv_bfloat16* Ch = g_Chi + (size_t)b * DD * NN;
    const __nv_bfloat16* Cl = g_Clo + (size_t)b * DD * NN;
    int wm = (wid & 1) * 64, wn = (wid >> 1) * 32;
    int g = lane >> 2, t4 = lane & 3;
    float acc[4][4][4] = {};
    int ar = tid >> 1, ac = (tid & 1) * 2, asw = (ar >> 1) & 3;
    int kp = tid & 15, mb = tid >> 4;
    __syncthreads();
    for (int c = 0; c < NN / KB; c++) {
        int n0 = c * KB;
        {
            const uint4* ph = (const uint4*)(Ch + (size_t)ar * NN + n0);
            const uint4* pl = (const uint4*)(Cl + (size_t)ar * NN + n0);
            ((uint4*)AH)[ar * 4 + (ac ^ asw)]       = ph[ac];
            ((uint4*)AH)[ar * 4 + ((ac + 1) ^ asw)] = ph[ac + 1];
            ((uint4*)AL)[ar * 4 + (ac ^ asw)]       = pl[ac];
            ((uint4*)AL)[ar * 4 + ((ac + 1) ^ asw)] = pl[ac + 1];
        }
        {
            const float* s0 = Sb + (size_t)(n0 + 2 * kp) * MM + m0 + mb * 8;
            const float* s1 = s0 + MM;
            float4 x0 = *(const float4*)s0, x1 = *(const float4*)(s0 + 4);
            float4 y0 = *(const float4*)s1, y1 = *(const float4*)(s1 + 4);
            float xs[8] = {x0.x, x0.y, x0.z, x0.w, x1.x, x1.y, x1.z, x1.w};
            float ys[8] = {y0.x, y0.y, y0.z, y0.w, y1.x, y1.y, y1.z, y1.w};
#pragma unroll
            for (int i = 0; i < 8; i++) {
                int m = mb * 8 + i;
                float L = l2s[m];
                float e0 = fexp(xs[i] - L), e1 = fexp(ys[i] - L);
                int w = m * 16 + (kp ^ (((m >> 1) & 3) << 2));
                EH[w] = packsplit_hi(e0, e1);
                EL[w] = packsplit_lo(e0, e1);
            }
        }
        __syncthreads();
#pragma unroll
        for (int ks = 0; ks < 2; ks++) {
            uint32_t bh[4][2], bl[4][2];
#pragma unroll
            for (int nt = 0; nt < 4; nt++) {
                int j = wn + nt * 8 + g;
                int sj = ((j >> 1) & 3) << 2;
                int w0 = j * 16 + ((ks * 8 + t4) ^ sj);
                int w1 = j * 16 + ((ks * 8 + 4 + t4) ^ sj);
                bh[nt][0] = EH[w0]; bh[nt][1] = EH[w1];
                bl[nt][0] = EL[w0]; bl[nt][1] = EL[w1];
            }
#pragma unroll
            for (int mt = 0; mt < 4; mt++) {
                int m = wm + mt * 16 + g;
                int sw = ((m >> 1) & 3) << 2;
                int w0 = (ks * 8 + t4) ^ sw, w1 = (ks * 8 + 4 + t4) ^ sw;
                uint32_t ah[4] = {AH[m * 16 + w0], AH[(m + 8) * 16 + w0],
                                  AH[m * 16 + w1], AH[(m + 8) * 16 + w1]};
                uint32_t al[4] = {AL[m * 16 + w0], AL[(m + 8) * 16 + w0],
                                  AL[m * 16 + w1], AL[(m + 8) * 16 + w1]};
#pragma unroll
                for (int nt = 0; nt < 4; nt++) {
                    mma16816(acc[mt][nt], ah, bh[nt]);
                    mma16816(acc[mt][nt], ah, bl[nt]);
                    mma16816(acc[mt][nt], al, bh[nt]);
                }
            }
        }
        __syncthreads();
    }
#pragma unroll
    for (int mt = 0; mt < 4; mt++) {
#pragma unroll
        for (int nt = 0; nt < 4; nt++) {
            float* cfr = acc[mt][nt];
            int d0 = wm + mt * 16 + g;
            int col = m0 + wn + nt * 8 + t4 * 2;
            size_t o0 = (size_t)(b * DD + d0) * MM + col;
            size_t o1 = (size_t)(b * DD + d0 + 8) * MM + col;
            *(uint32_t*)(g_CBhi + o0) = packsplit_hi(cfr[0], cfr[1]);
            *(uint32_t*)(g_CBlo + o0) = packsplit_lo(cfr[0], cfr[1]);
            *(uint32_t*)(g_CBhi + o1) = packsplit_hi(cfr[2], cfr[3]);
            *(uint32_t*)(g_CBlo + o1) = packsplit_lo(cfr[2], cfr[3]);
        }
    }
}

// ---- stage 4: A (z=0) / Bt (z=1) ----
__global__ __launch_bounds__(256) void ab_mma() {
    extern __shared__ char smc[];
    float* l1s = (float*)smc;
    uint32_t* AH = (uint32_t*)(smc + 512);
    uint32_t* AL = AH + T_WORDS;
    uint32_t* EH = AL + T_WORDS;
    uint32_t* EL = EH + T_WORDS;
    int tid = threadIdx.x, lane = tid & 31, wid = tid >> 5;
    int b = blockIdx.y, n0 = blockIdx.x * 128, z = blockIdx.z;
    if (tid < 128) l1s[tid] = g_L1[b * NN + n0 + tid];
    const float* Sb = g_S + (size_t)b * NN * MM;
    const __nv_bfloat16* Xh = (z ? g_CBhi : g_Qhi) + (size_t)b * DD * MM;
    const __nv_bfloat16* Xl = (z ? g_CBlo : g_Qlo) + (size_t)b * DD * MM;
    float* Out = (z ? g_Bt : g_A) + (size_t)b * DD * NN;
    int wm = (wid & 1) * 64, wn = (wid >> 1) * 32;
    int g = lane >> 2, t4 = lane & 3;
    float acc[4][4][4] = {};
    int ar = tid >> 1, ac = (tid & 1) * 2, asw = (ar >> 1) & 3;
    int nr = tid >> 1, half = tid & 1;
    __syncthreads();
    for (int c = 0; c < MM / KB; c++) {
        int mc0 = c * KB;
        {
            const uint4* ph = (const uint4*)(Xh + (size_t)ar * MM + mc0);
            const uint4* pl = (const uint4*)(Xl + (size_t)ar * MM + mc0);
            ((uint4*)AH)[ar * 4 + (ac ^ asw)]       = ph[ac];
            ((uint4*)AH)[ar * 4 + ((ac + 1) ^ asw)] = ph[ac + 1];
            ((uint4*)AL)[ar * 4 + (ac ^ asw)]       = pl[ac];
            ((uint4*)AL)[ar * 4 + ((ac + 1) ^ asw)] = pl[ac + 1];
        }
        {
            const float* sp = Sb + (size_t)(n0 + nr) * MM + mc0 + half * 16;
            float4 v0 = *(const float4*)sp, v1 = *(const float4*)(sp + 4);
            float4 v2 = *(const float4*)(sp + 8), v3 = *(const float4*)(sp + 12);
            float vs[16] = {v0.x, v0.y, v0.z, v0.w, v1.x, v1.y, v1.z, v1.w,
                            v2.x, v2.y, v2.z, v2.w, v3.x, v3.y, v3.z, v3.w};
            float L = l1s[nr];
            int sn = ((nr >> 1) & 3) << 2;
#pragma unroll
            for (int q = 0; q < 8; q++) {
                float e0 = fexp(vs[2 * q] - L), e1 = fexp(vs[2 * q + 1] - L);
                int w = nr * 16 + ((half * 8 + q) ^ sn);
                EH[w] = packsplit_hi(e0, e1);
                EL[w] = packsplit_lo(e0, e1);
            }
        }
        __syncthreads();
#pragma unroll
        for (int ks = 0; ks < 2; ks++) {
            uint32_t bh[4][2], bl[4][2];
#pragma unroll
            for (int nt = 0; nt < 4; nt++) {
                int j = wn + nt * 8 + g;
                int sj = ((j >> 1) & 3) << 2;
                int w0 = j * 16 + ((ks * 8 + t4) ^ sj);
                int w1 = j * 16 + ((ks * 8 + 4 + t4) ^ sj);
                bh[nt][0] = EH[w0]; bh[nt][1] = EH[w1];
                bl[nt][0] = EL[w0]; bl[nt][1] = EL[w1];
            }
#pragma unroll
            for (int mt = 0; mt < 4; mt++) {
                int m = wm + mt * 16 + g;
                int sw = ((m >> 1) & 3) << 2;
                int w0 = (ks * 8 + t4) ^ sw, w1 = (ks * 8 + 4 + t4) ^ sw;
                uint32_t ah[4] = {AH[m * 16 + w0], AH[(m + 8) * 16 + w0],
                                  AH[m * 16 + w1], AH[(m + 8) * 16 + w1]};
                uint32_t al[4] = {AL[m * 16 + w0], AL[(m + 8) * 16 + w0],
                                  AL[m * 16 + w1], AL[(m + 8) * 16 + w1]};
#pragma unroll
                for (int nt = 0; nt < 4; nt++) {
                    mma16816(acc[mt][nt], ah, bh[nt]);
                    mma16816(acc[mt][nt], ah, bl[nt]);
                    mma16816(acc[mt][nt], al, bh[nt]);
                }
            }
        }
        __syncthreads();
    }
#pragma unroll
    for (int mt = 0; mt < 4; mt++) {
#pragma unroll
        for (int nt = 0; nt < 4; nt++) {
            float* cfr = acc[mt][nt];
            int r0 = wm + mt * 16 + g;
            int col = n0 + wn + nt * 8 + t4 * 2;
            *(float2*)(Out + (size_t)r0 * NN + col)       = make_float2(cfr[0], cfr[1]);
            *(float2*)(Out + (size_t)(r0 + 8) * NN + col) = make_float2(cfr[2], cfr[3]);
        }
    }
}

// ---- stage 5: concat + dropout ----
__device__ __forceinline__ void write_drop4(float* p, size_t idx, float4 v) {
    float4 o;
    o.x = dropscale((uint32_t)(idx + 0), v.x);
    o.y = dropscale((uint32_t)(idx + 1), v.y);
    o.z = dropscale((uint32_t)(idx + 2), v.z);
    o.w = dropscale((uint32_t)(idx + 3), v.w);
    *(float4*)p = o;
}
__global__ __launch_bounds__(256) void epilogue_kernel(const float* __restrict__ C,
                                                       float* __restrict__ out) {
    unsigned gi = blockIdx.x * 256u + threadIdx.x;
    unsigned t = gi & 511u, bd = gi >> 9, d = bd & 127u, b = bd >> 7, n = t * 4u;
    size_t src = ((size_t)(b * DD + d)) * NN + n;
    float4 c = *(const float4*)(C + src);
    float4 a = *(const float4*)(g_A + src);
    float4 bt = *(const float4*)(g_Bt + src);
    float4 ca = make_float4(c.x * a.x, c.y * a.y, c.z * a.z, c.w * a.w);
    float4 cbt = make_float4(c.x * bt.x, c.y * bt.y, c.z * bt.z, c.w * bt.w);
    size_t o0 = ((size_t)b * 4 * DD + d) * NN + n;
    const size_t st = (size_t)DD * NN;
    write_drop4(out + o0, o0, c);
    write_drop4(out + o0 + st, o0 + st, a);
    write_drop4(out + o0 + 2 * st, o0 + 2 * st, ca);
    write_drop4(out + o0 + 3 * st, o0 + 3 * st, cbt);
}

// ---- launch ----
#define MMA_SMEM (512 + 4 * 8192)
extern "C" void kernel_launch(void* const* d_in, const int* in_sizes, int n_in,
                              void* d_out, int out_size) {
    const float* C = (const float*)d_in[0];
    const float* Q = (const float*)d_in[1];
    const float* W = (const float*)d_in[2];
    float* out = (float*)d_out;
    bias_kernel<<<dim3(MM / 256, BB, 2), 256>>>(C, Q, W);
    split_cq_kernel<<<dim3((BB * DD * NN / 4) / 256, 2), 256>>>(C, Q);
    tsplit_kernel<<<dim3(NN / 32, DD / 32, BB * 2), 256>>>(C, Q, W);
    s_mma<<<dim3(MM / 128, NN / 128, BB), 256, G1_SMEM>>>();
    rowcombine_kernel<<<dim3((BB * NN) / 256), 256>>>();
    colcombine_kernel<<<dim3((BB * MM) / 256), 256>>>();
    cb_mma<<<dim3(MM / 128, BB), 256, MMA_SMEM>>>();
    ab_mma<<<dim3(NN / 128, BB, 2), 256, MMA_SMEM>>>();
    epilogue_kernel<<<dim3((BB * DD * NN / 4) / 256), 256>>>(C, out);
}

// round 10
// speedup vs baseline: 1.7222x; 1.0176x over previous
#include <cuda_runtime.h>
#include <cuda_bf16.h>
#include <cstdint>
#include <cstddef>

#define BB 24
#define DD 128
#define NN 2048
#define MM 2048
#define KB 32
#define T_WORDS 2048

__device__ float g_S [(size_t)BB * NN * MM];
__device__ float g_A [(size_t)BB * DD * NN];
__device__ float g_Bt[(size_t)BB * DD * NN];
__device__ float g_L1[BB * NN];
__device__ float g_L2[BB * MM];
__device__ float g_sq[BB * MM];
__device__ float g_sc[BB * NN];
__device__ float2 g_rowp[(size_t)BB * 16 * NN];
__device__ float2 g_colp[(size_t)BB * 16 * MM];
__device__ __nv_bfloat16 g_Chi[(size_t)BB * DD * NN];
__device__ __nv_bfloat16 g_Clo[(size_t)BB * DD * NN];
__device__ __nv_bfloat16 g_Qhi[(size_t)BB * DD * MM];
__device__ __nv_bfloat16 g_Qlo[(size_t)BB * DD * MM];
__device__ __nv_bfloat16 g_CBhi[(size_t)BB * DD * MM];
__device__ __nv_bfloat16 g_CBlo[(size_t)BB * DD * MM];
__device__ __nv_bfloat16 g_CThi[(size_t)BB * NN * DD];
__device__ __nv_bfloat16 g_CTlo[(size_t)BB * NN * DD];
__device__ __nv_bfloat16 g_QWhi[(size_t)BB * MM * DD];
__device__ __nv_bfloat16 g_QWlo[(size_t)BB * MM * DD];

// ---- warp mma (baseline sm_80+ HMMA) ----
__device__ __forceinline__ void mma16816(float* c, const uint32_t* a, const uint32_t* b) {
    asm volatile("mma.sync.aligned.m16n8k16.row.col.f32.bf16.bf16.f32 "
                 "{%0,%1,%2,%3},{%4,%5,%6,%7},{%8,%9},{%0,%1,%2,%3};"
                 : "+f"(c[0]), "+f"(c[1]), "+f"(c[2]), "+f"(c[3])
                 : "r"(a[0]), "r"(a[1]), "r"(a[2]), "r"(a[3]), "r"(b[0]), "r"(b[1]));
}

__device__ __forceinline__ void splitf(float x, uint16_t& h, uint16_t& l) {
    __nv_bfloat16 bh = __float2bfloat16_rn(x);
    float r = x - __bfloat162float(bh);
    __nv_bfloat16 bl = __float2bfloat16_rn(r);
    h = __bfloat16_as_ushort(bh); l = __bfloat16_as_ushort(bl);
}
__device__ __forceinline__ uint32_t packsplit_hi(float a, float b) {
    uint16_t h0, l0, h1, l1; splitf(a, h0, l0); splitf(b, h1, l1);
    return (uint32_t)h0 | ((uint32_t)h1 << 16);
}
__device__ __forceinline__ uint32_t packsplit_lo(float a, float b) {
    uint16_t h0, l0, h1, l1; splitf(a, h0, l0); splitf(b, h1, l1);
    return (uint32_t)l0 | ((uint32_t)l1 << 16);
}
// fast exp on FMA pipe (rel err ~2.4e-6)
__device__ __forceinline__ float fexp(float x) {
    float t = fmaxf(x * 1.4426950408889634f, -126.0f);
    float kf = t + 12582912.0f;
    float fi = kf - 12582912.0f;
    float f = t - fi;
    float p = 1.3333558146e-3f;
    p = fmaf(p, f, 9.6181291076e-3f);
    p = fmaf(p, f, 5.5504108665e-2f);
    p = fmaf(p, f, 2.4022650696e-1f);
    p = fmaf(p, f, 6.9314718056e-1f);
    p = fmaf(p, f, 1.0f);
    return __int_as_float(__float_as_int(p) + (((int)fi) << 23));
}

// ---- threefry2x32, JAX partitionable, key=(0,42) ----
__device__ __forceinline__ uint32_t rotl32(uint32_t x, int r) { return __funnelshift_l(x, x, r); }
#define TF_ROUND4(a, b, c, d)                       \
    x0 += x1; x1 = rotl32(x1, a); x1 ^= x0;         \
    x0 += x1; x1 = rotl32(x1, b); x1 ^= x0;         \
    x0 += x1; x1 = rotl32(x1, c); x1 ^= x0;         \
    x0 += x1; x1 = rotl32(x1, d); x1 ^= x0;
__device__ __forceinline__ uint32_t threefry_bits(uint32_t idx) {
    const uint32_t ks0 = 0u, ks1 = 42u;
    const uint32_t ks2 = 0x1BD11BDAu ^ ks0 ^ ks1;
    uint32_t x0 = 0u + ks0, x1 = idx + ks1;
    TF_ROUND4(13, 15, 26, 6)  x0 += ks1; x1 += ks2 + 1u;
    TF_ROUND4(17, 29, 16, 24) x0 += ks2; x1 += ks0 + 2u;
    TF_ROUND4(13, 15, 26, 6)  x0 += ks0; x1 += ks1 + 3u;
    TF_ROUND4(17, 29, 16, 24) x0 += ks1; x1 += ks2 + 4u;
    TF_ROUND4(13, 15, 26, 6)  x0 += ks2; x1 += ks0 + 5u;
    return x0 ^ x1;
}
__device__ __forceinline__ float dropscale(uint32_t idx, float v) {
    uint32_t bits = threefry_bits(idx);
    float u = __uint_as_float((bits >> 9) | 0x3f800000u) - 1.0f;
    return (u < 0.9f) ? v * (1.0f / 0.9f) : 0.0f;
}

// ---- stage 0: biases ----
__global__ __launch_bounds__(256) void bias_kernel(const float* __restrict__ C,
                                                   const float* __restrict__ Q,
                                                   const float* __restrict__ W) {
    int b = blockIdx.y;
    int m = blockIdx.x * 256 + threadIdx.x;
    const float* X; const float* wv; float* out;
    if (blockIdx.z == 0) { X = Q + (size_t)b * DD * MM; wv = W + b * 3 * DD;      out = g_sq + b * MM; }
    else                 { X = C + (size_t)b * DD * NN; wv = W + b * 3 * DD + DD; out = g_sc + b * NN; }
    __shared__ float ws[DD];
    if (threadIdx.x < DD) ws[threadIdx.x] = wv[threadIdx.x];
    __syncthreads();
    float acc = 0.0f;
#pragma unroll 8
    for (int d = 0; d < DD; d++) acc = fmaf(ws[d], X[(size_t)d * MM + m], acc);
    out[m] = acc;
}

// ---- stage 0b: split C,Q in [d][*] layout (consumers) ----
__global__ __launch_bounds__(256) void split_cq_kernel(const float* __restrict__ C,
                                                       const float* __restrict__ Q) {
    size_t i = ((size_t)blockIdx.x * 256 + threadIdx.x) * 4;
    const float* src; __nv_bfloat16 *dh, *dl;
    if (blockIdx.y == 0) { src = C; dh = g_Chi; dl = g_Clo; }
    else                 { src = Q; dh = g_Qhi; dl = g_Qlo; }
    float4 v = *(const float4*)(src + i);
    *(uint2*)(dh + i) = make_uint2(packsplit_hi(v.x, v.y), packsplit_hi(v.z, v.w));
    *(uint2*)(dl + i) = make_uint2(packsplit_lo(v.x, v.y), packsplit_lo(v.z, v.w));
}

// ---- stage 0c: transpose-split for s_mma: CT[n][d], QW[m][d] (Wm folded) ----
__global__ __launch_bounds__(256) void tsplit_kernel(const float* __restrict__ C,
                                                     const float* __restrict__ Q,
                                                     const float* __restrict__ W) {
    __shared__ float ts[32][33];
    __shared__ float wsc[32];
    int z = blockIdx.z, b = z >> 1, isQ = z & 1;
    int n0 = blockIdx.x * 32, d0 = blockIdx.y * 32;
    const float* X = (isQ ? Q : C) + (size_t)b * DD * NN;
    int t = threadIdx.x, nl = t & 31, dr = t >> 5;
    if (t < 32) wsc[t] = isQ ? W[b * 3 * DD + 2 * DD + d0 + t] : 1.0f;
#pragma unroll
    for (int k = 0; k < 4; k++)
        ts[dr + k * 8][nl] = X[(size_t)(d0 + dr + k * 8) * NN + n0 + nl];
    __syncthreads();
    int nr = t >> 3, dg = (t & 7) * 4;
    __nv_bfloat16* dh = (isQ ? g_QWhi : g_CThi) + ((size_t)b * NN + n0 + nr) * DD + d0 + dg;
    __nv_bfloat16* dl = (isQ ? g_QWlo : g_CTlo) + ((size_t)b * NN + n0 + nr) * DD + d0 + dg;
    float v0 = ts[dg][nr] * wsc[dg],     v1 = ts[dg + 1][nr] * wsc[dg + 1];
    float v2 = ts[dg + 2][nr] * wsc[dg + 2], v3 = ts[dg + 3][nr] * wsc[dg + 3];
    *(uint2*)dh = make_uint2(packsplit_hi(v0, v1), packsplit_hi(v2, v3));
    *(uint2*)dl = make_uint2(packsplit_lo(v0, v1), packsplit_lo(v2, v3));
}

// ---- stage 1: S = CT * QW^T via HMMA + biases + fused stats ----
#define G1_SMEM (1024 + 4 * 8192)
__global__ __launch_bounds__(256) void s_mma() {
    extern __shared__ char smc[];
    float* sc_s = (float*)smc;
    float* sq_s = (float*)(smc + 512);
    uint32_t* AH = (uint32_t*)(smc + 1024);
    uint32_t* AL = AH + T_WORDS;
    uint32_t* BH = AL + T_WORDS;
    uint32_t* BL = BH + T_WORDS;
    float* st  = (float*)(smc + 1024);
    float* rm4 = st;
    float* rfin = st + 512;
    float* rs4 = st + 640;
    float* cm2 = st + 1152;
    float* cfin = st + 1408;
    float* cs2 = st + 1536;
    int tid = threadIdx.x, lane = tid & 31, wid = tid >> 5;
    int b = blockIdx.z, n0 = blockIdx.y * 128, m0 = blockIdx.x * 128;
    if (tid < 128) { sc_s[tid] = g_sc[b * NN + n0 + tid]; sq_s[tid] = g_sq[b * MM + m0 + tid]; }
    const __nv_bfloat16* Ahg = g_CThi + ((size_t)b * NN + n0) * DD;
    const __nv_bfloat16* Alg = g_CTlo + ((size_t)b * NN + n0) * DD;
    const __nv_bfloat16* Bhg = g_QWhi + ((size_t)b * MM + m0) * DD;
    const __nv_bfloat16* Blg = g_QWlo + ((size_t)b * MM + m0) * DD;
    int wm = (wid & 1) * 64, wn = (wid >> 1) * 32;
    int g = lane >> 2, t4 = lane & 3;
    float acc[4][4][4] = {};
    int ar = tid >> 1, ac = (tid & 1) * 2, asw = (ar >> 1) & 3;
    __syncthreads();
    for (int c = 0; c < 4; c++) {
        const uint4* pah = (const uint4*)(Ahg + (size_t)ar * DD + c * 32);
        const uint4* pal = (const uint4*)(Alg + (size_t)ar * DD + c * 32);
        const uint4* pbh = (const uint4*)(Bhg + (size_t)ar * DD + c * 32);
        const uint4* pbl = (const uint4*)(Blg + (size_t)ar * DD + c * 32);
        ((uint4*)AH)[ar * 4 + (ac ^ asw)]       = pah[ac];
        ((uint4*)AH)[ar * 4 + ((ac + 1) ^ asw)] = pah[ac + 1];
        ((uint4*)AL)[ar * 4 + (ac ^ asw)]       = pal[ac];
        ((uint4*)AL)[ar * 4 + ((ac + 1) ^ asw)] = pal[ac + 1];
        ((uint4*)BH)[ar * 4 + (ac ^ asw)]       = pbh[ac];
        ((uint4*)BH)[ar * 4 + ((ac + 1) ^ asw)] = pbh[ac + 1];
        ((uint4*)BL)[ar * 4 + (ac ^ asw)]       = pbl[ac];
        ((uint4*)BL)[ar * 4 + ((ac + 1) ^ asw)] = pbl[ac + 1];
        __syncthreads();
#pragma unroll
        for (int ks = 0; ks < 2; ks++) {
            uint32_t bh[4][2], bl[4][2];
#pragma unroll
            for (int nt = 0; nt < 4; nt++) {
                int j = wn + nt * 8 + g;
                int sj = ((j >> 1) & 3) << 2;
                int w0 = j * 16 + ((ks * 8 + t4) ^ sj);
                int w1 = j * 16 + ((ks * 8 + 4 + t4) ^ sj);
                bh[nt][0] = BH[w0]; bh[nt][1] = BH[w1];
                bl[nt][0] = BL[w0]; bl[nt][1] = BL[w1];
            }
#pragma unroll
            for (int mt = 0; mt < 4; mt++) {
                int m = wm + mt * 16 + g;
                int sw = ((m >> 1) & 3) << 2;
                int w0 = (ks * 8 + t4) ^ sw, w1 = (ks * 8 + 4 + t4) ^ sw;
                uint32_t ah[4] = {AH[m * 16 + w0], AH[(m + 8) * 16 + w0],
                                  AH[m * 16 + w1], AH[(m + 8) * 16 + w1]};
                uint32_t al[4] = {AL[m * 16 + w0], AL[(m + 8) * 16 + w0],
                                  AL[m * 16 + w1], AL[(m + 8) * 16 + w1]};
#pragma unroll
                for (int nt = 0; nt < 4; nt++) {
                    mma16816(acc[mt][nt], ah, bh[nt]);
                    mma16816(acc[mt][nt], ah, bl[nt]);
                    mma16816(acc[mt][nt], al, bh[nt]);
                }
            }
        }
        __syncthreads();
    }
    float* Sb = g_S + (size_t)b * NN * MM;
#pragma unroll
    for (int mt = 0; mt < 4; mt++) {
#pragma unroll
        for (int nt = 0; nt < 4; nt++) {
            int r0 = wm + mt * 16 + g, c0 = wn + nt * 8 + t4 * 2;
            acc[mt][nt][0] += sc_s[r0] + sq_s[c0];
            acc[mt][nt][1] += sc_s[r0] + sq_s[c0 + 1];
            acc[mt][nt][2] += sc_s[r0 + 8] + sq_s[c0];
            acc[mt][nt][3] += sc_s[r0 + 8] + sq_s[c0 + 1];
            *(float2*)(Sb + (size_t)(n0 + r0) * MM + m0 + c0)     = make_float2(acc[mt][nt][0], acc[mt][nt][1]);
            *(float2*)(Sb + (size_t)(n0 + r0 + 8) * MM + m0 + c0) = make_float2(acc[mt][nt][2], acc[mt][nt][3]);
        }
    }
#pragma unroll
    for (int mt = 0; mt < 4; mt++) {
#pragma unroll
        for (int h = 0; h < 2; h++) {
            float m = acc[mt][0][h * 2];
#pragma unroll
            for (int nt = 0; nt < 4; nt++) {
                m = fmaxf(m, acc[mt][nt][h * 2]);
                m = fmaxf(m, acc[mt][nt][h * 2 + 1]);
            }
            m = fmaxf(m, __shfl_xor_sync(0xffffffffu, m, 1));
            m = fmaxf(m, __shfl_xor_sync(0xffffffffu, m, 2));
            if (t4 == 0) rm4[(wid >> 1) * 128 + wm + mt * 16 + g + 8 * h] = m;
        }
    }
    __syncthreads();
    if (tid < 128)
        rfin[tid] = fmaxf(fmaxf(rm4[tid], rm4[128 + tid]), fmaxf(rm4[256 + tid], rm4[384 + tid]));
    __syncthreads();
#pragma unroll
    for (int mt = 0; mt < 4; mt++) {
#pragma unroll
        for (int h = 0; h < 2; h++) {
            int r = wm + mt * 16 + g + 8 * h;
            float L = rfin[r], s = 0.0f;
#pragma unroll
            for (int nt = 0; nt < 4; nt++)
                s += fexp(acc[mt][nt][h * 2] - L) + fexp(acc[mt][nt][h * 2 + 1] - L);
            s += __shfl_xor_sync(0xffffffffu, s, 1);
            s += __shfl_xor_sync(0xffffffffu, s, 2);
            if (t4 == 0) rs4[(wid >> 1) * 128 + r] = s;
        }
    }
    __syncthreads();
    if (tid < 128)
        g_rowp[((size_t)(b * 16 + (m0 >> 7))) * NN + n0 + tid] =
            make_float2(rfin[tid], rs4[tid] + rs4[128 + tid] + rs4[256 + tid] + rs4[384 + tid]);
#pragma unroll
    for (int nt = 0; nt < 4; nt++) {
#pragma unroll
        for (int e = 0; e < 2; e++) {
            float m = acc[0][nt][e];
#pragma unroll
            for (int mt = 0; mt < 4; mt++) {
                m = fmaxf(m, acc[mt][nt][e]);
                m = fmaxf(m, acc[mt][nt][2 + e]);
            }
            m = fmaxf(m, __shfl_xor_sync(0xffffffffu, m, 4));
            m = fmaxf(m, __shfl_xor_sync(0xffffffffu, m, 8));
            m = fmaxf(m, __shfl_xor_sync(0xffffffffu, m, 16));
            if (g == 0) cm2[(wid & 1) * 128 + wn + nt * 8 + t4 * 2 + e] = m;
        }
    }
    __syncthreads();
    if (tid < 128) cfin[tid] = fmaxf(cm2[tid], cm2[128 + tid]);
    __syncthreads();
#pragma unroll
    for (int nt = 0; nt < 4; nt++) {
#pragma unroll
        for (int e = 0; e < 2; e++) {
            int c = wn + nt * 8 + t4 * 2 + e;
            float L = cfin[c], s = 0.0f;
#pragma unroll
            for (int mt = 0; mt < 4; mt++)
                s += fexp(acc[mt][nt][e] - L) + fexp(acc[mt][nt][2 + e] - L);
            s += __shfl_xor_sync(0xffffffffu, s, 4);
            s += __shfl_xor_sync(0xffffffffu, s, 8);
            s += __shfl_xor_sync(0xffffffffu, s, 16);
            if (g == 0) cs2[(wid & 1) * 128 + c] = s;
        }
    }
    __syncthreads();
    if (tid < 128)
        g_colp[((size_t)(b * 16 + (n0 >> 7))) * MM + m0 + tid] =
            make_float2(cfin[tid], cs2[tid] + cs2[128 + tid]);
}

// ---- stage 2: combines ----
__global__ __launch_bounds__(256) void rowcombine_kernel() {
    int idx = blockIdx.x * 256 + threadIdx.x;
    int b = idx >> 11, n = idx & (NN - 1);
    const float2* p = g_rowp + (size_t)(b * 16) * NN + n;
    float2 f = p[0]; float mx = f.x, s = f.y;
#pragma unroll
    for (int t = 1; t < 16; t++) {
        float2 g = p[(size_t)t * NN];
        float nm = fmaxf(mx, g.x);
        s = s * __expf(mx - nm) + g.y * __expf(g.x - nm); mx = nm;
    }
    g_L1[idx] = mx + logf(s);
}
__global__ __launch_bounds__(256) void colcombine_kernel() {
    int idx = blockIdx.x * 256 + threadIdx.x;
    int b = idx >> 11, m = idx & (MM - 1);
    const float2* p = g_colp + (size_t)(b * 16) * MM + m;
    float2 f = p[0]; float mx = f.x, s = f.y;
#pragma unroll
    for (int t = 1; t < 16; t++) {
        float2 g = p[(size_t)t * MM];
        float nm = fmaxf(mx, g.x);
        s = s * __expf(mx - nm) + g.y * __expf(g.x - nm); mx = nm;
    }
    g_L2[idx] = mx + logf(s);
}

// ---- stage 3: CB = C * E2 via HMMA ----
__global__ __launch_bounds__(256) void cb_mma() {
    extern __shared__ char smc[];
    float* l2s = (float*)smc;
    uint32_t* AH = (uint32_t*)(smc + 512);
    uint32_t* AL = AH + T_WORDS;
    uint32_t* EH = AL + T_WORDS;
    uint32_t* EL = EH + T_WORDS;
    int tid = threadIdx.x, lane = tid & 31, wid = tid >> 5;
    int b = blockIdx.y, m0 = blockIdx.x * 128;
    if (tid < 128) l2s[tid] = g_L2[b * MM + m0 + tid];
    const float* Sb = g_S + (size_t)b * NN * MM;
    const __nv_bfloat16* Ch = g_Chi + (size_t)b * DD * NN;
    const __nv_bfloat16* Cl = g_Clo + (size_t)b * DD * NN;
    int wm = (wid & 1) * 64, wn = (wid >> 1) * 32;
    int g = lane >> 2, t4 = lane & 3;
    float acc[4][4][4] = {};
    int ar = tid >> 1, ac = (tid & 1) * 2, asw = (ar >> 1) & 3;
    int kp = tid & 15, mb = tid >> 4;
    __syncthreads();
    for (int c = 0; c < NN / KB; c++) {
        int n0 = c * KB;
        {
            const uint4* ph = (const uint4*)(Ch + (size_t)ar * NN + n0);
            const uint4* pl = (const uint4*)(Cl + (size_t)ar * NN + n0);
            ((uint4*)AH)[ar * 4 + (ac ^ asw)]       = ph[ac];
            ((uint4*)AH)[ar * 4 + ((ac + 1) ^ asw)] = ph[ac + 1];
            ((uint4*)AL)[ar * 4 + (ac ^ asw)]       = pl[ac];
            ((uint4*)AL)[ar * 4 + ((ac + 1) ^ asw)] = pl[ac + 1];
        }
        {
            const float* s0 = Sb + (size_t)(n0 + 2 * kp) * MM + m0 + mb * 8;
            const float* s1 = s0 + MM;
            float4 x0 = *(const float4*)s0, x1 = *(const float4*)(s0 + 4);
            float4 y0 = *(const float4*)s1, y1 = *(const float4*)(s1 + 4);
            float xs[8] = {x0.x, x0.y, x0.z, x0.w, x1.x, x1.y, x1.z, x1.w};
            float ys[8] = {y0.x, y0.y, y0.z, y0.w, y1.x, y1.y, y1.z, y1.w};
#pragma unroll
            for (int i = 0; i < 8; i++) {
                int m = mb * 8 + i;
                float L = l2s[m];
                float e0 = fexp(xs[i] - L), e1 = fexp(ys[i] - L);
                int w = m * 16 + (kp ^ (((m >> 1) & 3) << 2));
                EH[w] = packsplit_hi(e0, e1);
                EL[w] = packsplit_lo(e0, e1);
            }
        }
        __syncthreads();
#pragma unroll
        for (int ks = 0; ks < 2; ks++) {
            uint32_t bh[4][2], bl[4][2];
#pragma unroll
            for (int nt = 0; nt < 4; nt++) {
                int j = wn + nt * 8 + g;
                int sj = ((j >> 1) & 3) << 2;
                int w0 = j * 16 + ((ks * 8 + t4) ^ sj);
                int w1 = j * 16 + ((ks * 8 + 4 + t4) ^ sj);
                bh[nt][0] = EH[w0]; bh[nt][1] = EH[w1];
                bl[nt][0] = EL[w0]; bl[nt][1] = EL[w1];
            }
#pragma unroll
            for (int mt = 0; mt < 4; mt++) {
                int m = wm + mt * 16 + g;
                int sw = ((m >> 1) & 3) << 2;
                int w0 = (ks * 8 + t4) ^ sw, w1 = (ks * 8 + 4 + t4) ^ sw;
                uint32_t ah[4] = {AH[m * 16 + w0], AH[(m + 8) * 16 + w0],
                                  AH[m * 16 + w1], AH[(m + 8) * 16 + w1]};
                uint32_t al[4] = {AL[m * 16 + w0], AL[(m + 8) * 16 + w0],
                                  AL[m * 16 + w1], AL[(m + 8) * 16 + w1]};
#pragma unroll
                for (int nt = 0; nt < 4; nt++) {
                    mma16816(acc[mt][nt], ah, bh[nt]);
                    mma16816(acc[mt][nt], ah, bl[nt]);
                    mma16816(acc[mt][nt], al, bh[nt]);
                }
            }
        }
        __syncthreads();
    }
#pragma unroll
    for (int mt = 0; mt < 4; mt++) {
#pragma unroll
        for (int nt = 0; nt < 4; nt++) {
            float* cfr = acc[mt][nt];
            int d0 = wm + mt * 16 + g;
            int col = m0 + wn + nt * 8 + t4 * 2;
            size_t o0 = (size_t)(b * DD + d0) * MM + col;
            size_t o1 = (size_t)(b * DD + d0 + 8) * MM + col;
            *(uint32_t*)(g_CBhi + o0) = packsplit_hi(cfr[0], cfr[1]);
            *(uint32_t*)(g_CBlo + o0) = packsplit_lo(cfr[0], cfr[1]);
            *(uint32_t*)(g_CBhi + o1) = packsplit_hi(cfr[2], cfr[3]);
            *(uint32_t*)(g_CBlo + o1) = packsplit_lo(cfr[2], cfr[3]);
        }
    }
}

// ---- stage 4: fused A + Bt: block computes 128x64 slab of BOTH outputs ----
// warps 0-3 -> A (X=Q), warps 4-7 -> Bt (X=CB); shared E1 tile built once
#define ABF_SMEM (512 + 4 * 8192 + 2 * 4096)
__global__ __launch_bounds__(256) void abf_mma() {
    extern __shared__ char smc[];
    float* l1s = (float*)smc;
    uint32_t* QH = (uint32_t*)(smc + 512);
    uint32_t* QL = QH + 2048;
    uint32_t* BH = QL + 2048;
    uint32_t* BL = BH + 2048;
    uint32_t* EH = BL + 2048;
    uint32_t* EL = EH + 1024;
    int tid = threadIdx.x, lane = tid & 31, wid = tid >> 5;
    int b = blockIdx.y, n0 = blockIdx.x * 64;
    if (tid < 64) l1s[tid] = g_L1[b * NN + n0 + tid];
    const float* Sb = g_S + (size_t)b * NN * MM;
    const __nv_bfloat16* Qh = g_Qhi + (size_t)b * DD * MM;
    const __nv_bfloat16* Ql = g_Qlo + (size_t)b * DD * MM;
    const __nv_bfloat16* Bh = g_CBhi + (size_t)b * DD * MM;
    const __nv_bfloat16* Bl = g_CBlo + (size_t)b * DD * MM;
    int isBt = wid >> 2, wg = wid & 3;
    int wm = (wg & 1) * 64, wn = (wg >> 1) * 32;
    int g = lane >> 2, t4 = lane & 3;
    const uint32_t* XH = isBt ? BH : QH;
    const uint32_t* XL = isBt ? BL : QL;
    float acc[4][4][4] = {};
    int ar = tid >> 1, ac = (tid & 1) * 2, asw = (ar >> 1) & 3;
    int nr = tid >> 2, q4 = tid & 3;
    __syncthreads();
    for (int c = 0; c < MM / KB; c++) {
        int mc0 = c * KB;
        {   // X fills: Q and CB, hi/lo
            const uint4* pqh = (const uint4*)(Qh + (size_t)ar * MM + mc0);
            const uint4* pql = (const uint4*)(Ql + (size_t)ar * MM + mc0);
            const uint4* pbh = (const uint4*)(Bh + (size_t)ar * MM + mc0);
            const uint4* pbl = (const uint4*)(Bl + (size_t)ar * MM + mc0);
            ((uint4*)QH)[ar * 4 + (ac ^ asw)]       = pqh[ac];
            ((uint4*)QH)[ar * 4 + ((ac + 1) ^ asw)] = pqh[ac + 1];
            ((uint4*)QL)[ar * 4 + (ac ^ asw)]       = pql[ac];
            ((uint4*)QL)[ar * 4 + ((ac + 1) ^ asw)] = pql[ac + 1];
            ((uint4*)BH)[ar * 4 + (ac ^ asw)]       = pbh[ac];
            ((uint4*)BH)[ar * 4 + ((ac + 1) ^ asw)] = pbh[ac + 1];
            ((uint4*)BL)[ar * 4 + (ac ^ asw)]       = pbl[ac];
            ((uint4*)BL)[ar * 4 + ((ac + 1) ^ asw)] = pbl[ac + 1];
        }
        {   // E1 fill: 64 rows x 16 words; nr = row, q4 = word quad
            const float* sp = Sb + (size_t)(n0 + nr) * MM + mc0 + q4 * 8;
            float4 v0 = *(const float4*)sp, v1 = *(const float4*)(sp + 4);
            float vs[8] = {v0.x, v0.y, v0.z, v0.w, v1.x, v1.y, v1.z, v1.w};
            float L = l1s[nr];
            int sn = ((nr >> 1) & 3) << 2;
#pragma unroll
            for (int j = 0; j < 4; j++) {
                float e0 = fexp(vs[2 * j] - L), e1 = fexp(vs[2 * j + 1] - L);
                int w = nr * 16 + ((q4 * 4 + j) ^ sn);
                EH[w] = packsplit_hi(e0, e1);
                EL[w] = packsplit_lo(e0, e1);
            }
        }
        __syncthreads();
#pragma unroll
        for (int ks = 0; ks < 2; ks++) {
            uint32_t bh[4][2], bl[4][2];
#pragma unroll
            for (int nt = 0; nt < 4; nt++) {
                int j = wn + nt * 8 + g;
                int sj = ((j >> 1) & 3) << 2;
                int w0 = j * 16 + ((ks * 8 + t4) ^ sj);
                int w1 = j * 16 + ((ks * 8 + 4 + t4) ^ sj);
                bh[nt][0] = EH[w0]; bh[nt][1] = EH[w1];
                bl[nt][0] = EL[w0]; bl[nt][1] = EL[w1];
            }
#pragma unroll
            for (int mt = 0; mt < 4; mt++) {
                int m = wm + mt * 16 + g;
                int sw = ((m >> 1) & 3) << 2;
                int w0 = (ks * 8 + t4) ^ sw, w1 = (ks * 8 + 4 + t4) ^ sw;
                uint32_t ah[4] = {XH[m * 16 + w0], XH[(m + 8) * 16 + w0],
                                  XH[m * 16 + w1], XH[(m + 8) * 16 + w1]};
                uint32_t al[4] = {XL[m * 16 + w0], XL[(m + 8) * 16 + w0],
                                  XL[m * 16 + w1], XL[(m + 8) * 16 + w1]};
#pragma unroll
                for (int nt = 0; nt < 4; nt++) {
                    mma16816(acc[mt][nt], ah, bh[nt]);
                    mma16816(acc[mt][nt], ah, bl[nt]);
                    mma16816(acc[mt][nt], al, bh[nt]);
                }
            }
        }
        __syncthreads();
    }
    float* Out = (isBt ? g_Bt : g_A) + (size_t)b * DD * NN;
#pragma unroll
    for (int mt = 0; mt < 4; mt++) {
#pragma unroll
        for (int nt = 0; nt < 4; nt++) {
            float* cfr = acc[mt][nt];
            int r0 = wm + mt * 16 + g;
            int col = n0 + wn + nt * 8 + t4 * 2;
            *(float2*)(Out + (size_t)r0 * NN + col)       = make_float2(cfr[0], cfr[1]);
            *(float2*)(Out + (size_t)(r0 + 8) * NN + col) = make_float2(cfr[2], cfr[3]);
        }
    }
}

// ---- stage 5: concat + dropout ----
__device__ __forceinline__ void write_drop4(float* p, size_t idx, float4 v) {
    float4 o;
    o.x = dropscale((uint32_t)(idx + 0), v.x);
    o.y = dropscale((uint32_t)(idx + 1), v.y);
    o.z = dropscale((uint32_t)(idx + 2), v.z);
    o.w = dropscale((uint32_t)(idx + 3), v.w);
    *(float4*)p = o;
}
__global__ __launch_bounds__(256) void epilogue_kernel(const float* __restrict__ C,
                                                       float* __restrict__ out) {
    unsigned gi = blockIdx.x * 256u + threadIdx.x;
    unsigned t = gi & 511u, bd = gi >> 9, d = bd & 127u, b = bd >> 7, n = t * 4u;
    size_t src = ((size_t)(b * DD + d)) * NN + n;
    float4 c = *(const float4*)(C + src);
    float4 a = *(const float4*)(g_A + src);
    float4 bt = *(const float4*)(g_Bt + src);
    float4 ca = make_float4(c.x * a.x, c.y * a.y, c.z * a.z, c.w * a.w);
    float4 cbt = make_float4(c.x * bt.x, c.y * bt.y, c.z * bt.z, c.w * bt.w);
    size_t o0 = ((size_t)b * 4 * DD + d) * NN + n;
    const size_t st = (size_t)DD * NN;
    write_drop4(out + o0, o0, c);
    write_drop4(out + o0 + st, o0 + st, a);
    write_drop4(out + o0 + 2 * st, o0 + 2 * st, ca);
    write_drop4(out + o0 + 3 * st, o0 + 3 * st, cbt);
}

// ---- launch ----
#define MMA_SMEM (512 + 4 * 8192)
extern "C" void kernel_launch(void* const* d_in, const int* in_sizes, int n_in,
                              void* d_out, int out_size) {
    const float* C = (const float*)d_in[0];
    const float* Q = (const float*)d_in[1];
    const float* W = (const float*)d_in[2];
    float* out = (float*)d_out;
    bias_kernel<<<dim3(MM / 256, BB, 2), 256>>>(C, Q, W);
    split_cq_kernel<<<dim3((BB * DD * NN / 4) / 256, 2), 256>>>(C, Q);
    tsplit_kernel<<<dim3(NN / 32, DD / 32, BB * 2), 256>>>(C, Q, W);
    s_mma<<<dim3(MM / 128, NN / 128, BB), 256, G1_SMEM>>>();
    rowcombine_kernel<<<dim3((BB * NN) / 256), 256>>>();
    colcombine_kernel<<<dim3((BB * MM) / 256), 256>>>();
    cb_mma<<<dim3(MM / 128, BB), 256, MMA_SMEM>>>();
    abf_mma<<<dim3(NN / 64, BB), 256, ABF_SMEM>>>();
    epilogue_kernel<<<dim3((BB * DD * NN / 4) / 256), 256>>>(C, out);
}

// round 11
// speedup vs baseline: 1.9200x; 1.1148x over previous
#include <cuda_runtime.h>
#include <cuda_bf16.h>
#include <cstdint>
#include <cstddef>

#define BB 24
#define DD 128
#define NN 2048
#define MM 2048
#define KB 32
#define T_WORDS 2048

__device__ float g_S [(size_t)BB * NN * MM];
__device__ float g_A [(size_t)BB * DD * NN];
__device__ float g_Bt[(size_t)BB * DD * NN];
__device__ float g_L1[BB * NN];
__device__ float g_L2[BB * MM];
__device__ float g_sq[BB * MM];
__device__ float g_sc[BB * NN];
__device__ float2 g_rowp[(size_t)BB * 16 * NN];
__device__ float2 g_colp[(size_t)BB * 16 * MM];
__device__ __nv_bfloat16 g_Chi[(size_t)BB * DD * NN];
__device__ __nv_bfloat16 g_Clo[(size_t)BB * DD * NN];
__device__ __nv_bfloat16 g_Qhi[(size_t)BB * DD * MM];
__device__ __nv_bfloat16 g_Qlo[(size_t)BB * DD * MM];
__device__ __nv_bfloat16 g_CBhi[(size_t)BB * DD * MM];
__device__ __nv_bfloat16 g_CBlo[(size_t)BB * DD * MM];
__device__ __nv_bfloat16 g_CThi[(size_t)BB * NN * DD];
__device__ __nv_bfloat16 g_CTlo[(size_t)BB * NN * DD];
__device__ __nv_bfloat16 g_QWhi[(size_t)BB * MM * DD];
__device__ __nv_bfloat16 g_QWlo[(size_t)BB * MM * DD];

// ---- warp mma + ldmatrix ----
__device__ __forceinline__ void mma16816(float* c, const uint32_t* a, const uint32_t* b) {
    asm volatile("mma.sync.aligned.m16n8k16.row.col.f32.bf16.bf16.f32 "
                 "{%0,%1,%2,%3},{%4,%5,%6,%7},{%8,%9},{%0,%1,%2,%3};"
                 : "+f"(c[0]), "+f"(c[1]), "+f"(c[2]), "+f"(c[3])
                 : "r"(a[0]), "r"(a[1]), "r"(a[2]), "r"(a[3]), "r"(b[0]), "r"(b[1]));
}
__device__ __forceinline__ void ldsm4(uint32_t* r, uint32_t saddr) {
    asm volatile("ldmatrix.sync.aligned.m8n8.x4.shared.b16 {%0,%1,%2,%3}, [%4];"
                 : "=r"(r[0]), "=r"(r[1]), "=r"(r[2]), "=r"(r[3]) : "r"(saddr));
}
__device__ __forceinline__ uint32_t su32(const void* p) { return (uint32_t)__cvta_generic_to_shared(p); }

__device__ __forceinline__ void splitf(float x, uint16_t& h, uint16_t& l) {
    __nv_bfloat16 bh = __float2bfloat16_rn(x);
    float r = x - __bfloat162float(bh);
    __nv_bfloat16 bl = __float2bfloat16_rn(r);
    h = __bfloat16_as_ushort(bh); l = __bfloat16_as_ushort(bl);
}
__device__ __forceinline__ uint32_t packsplit_hi(float a, float b) {
    uint16_t h0, l0, h1, l1; splitf(a, h0, l0); splitf(b, h1, l1);
    return (uint32_t)h0 | ((uint32_t)h1 << 16);
}
__device__ __forceinline__ uint32_t packsplit_lo(float a, float b) {
    uint16_t h0, l0, h1, l1; splitf(a, h0, l0); splitf(b, h1, l1);
    return (uint32_t)l0 | ((uint32_t)l1 << 16);
}
// fast exp on FMA pipe (rel err ~2.4e-6)
__device__ __forceinline__ float fexp(float x) {
    float t = fmaxf(x * 1.4426950408889634f, -126.0f);
    float kf = t + 12582912.0f;
    float fi = kf - 12582912.0f;
    float f = t - fi;
    float p = 1.3333558146e-3f;
    p = fmaf(p, f, 9.6181291076e-3f);
    p = fmaf(p, f, 5.5504108665e-2f);
    p = fmaf(p, f, 2.4022650696e-1f);
    p = fmaf(p, f, 6.9314718056e-1f);
    p = fmaf(p, f, 1.0f);
    return __int_as_float(__float_as_int(p) + (((int)fi) << 23));
}

// ---- threefry2x32, JAX partitionable, key=(0,42) ----
__device__ __forceinline__ uint32_t rotl32(uint32_t x, int r) { return __funnelshift_l(x, x, r); }
#define TF_ROUND4(a, b, c, d)                       \
    x0 += x1; x1 = rotl32(x1, a); x1 ^= x0;         \
    x0 += x1; x1 = rotl32(x1, b); x1 ^= x0;         \
    x0 += x1; x1 = rotl32(x1, c); x1 ^= x0;         \
    x0 += x1; x1 = rotl32(x1, d); x1 ^= x0;
__device__ __forceinline__ uint32_t threefry_bits(uint32_t idx) {
    const uint32_t ks0 = 0u, ks1 = 42u;
    const uint32_t ks2 = 0x1BD11BDAu ^ ks0 ^ ks1;
    uint32_t x0 = 0u + ks0, x1 = idx + ks1;
    TF_ROUND4(13, 15, 26, 6)  x0 += ks1; x1 += ks2 + 1u;
    TF_ROUND4(17, 29, 16, 24) x0 += ks2; x1 += ks0 + 2u;
    TF_ROUND4(13, 15, 26, 6)  x0 += ks0; x1 += ks1 + 3u;
    TF_ROUND4(17, 29, 16, 24) x0 += ks1; x1 += ks2 + 4u;
    TF_ROUND4(13, 15, 26, 6)  x0 += ks2; x1 += ks0 + 5u;
    return x0 ^ x1;
}
__device__ __forceinline__ float dropscale(uint32_t idx, float v) {
    uint32_t bits = threefry_bits(idx);
    float u = __uint_as_float((bits >> 9) | 0x3f800000u) - 1.0f;
    return (u < 0.9f) ? v * (1.0f / 0.9f) : 0.0f;
}

// ---- stage 0: biases ----
__global__ __launch_bounds__(256) void bias_kernel(const float* __restrict__ C,
                                                   const float* __restrict__ Q,
                                                   const float* __restrict__ W) {
    int b = blockIdx.y;
    int m = blockIdx.x * 256 + threadIdx.x;
    const float* X; const float* wv; float* out;
    if (blockIdx.z == 0) { X = Q + (size_t)b * DD * MM; wv = W + b * 3 * DD;      out = g_sq + b * MM; }
    else                 { X = C + (size_t)b * DD * NN; wv = W + b * 3 * DD + DD; out = g_sc + b * NN; }
    __shared__ float ws[DD];
    if (threadIdx.x < DD) ws[threadIdx.x] = wv[threadIdx.x];
    __syncthreads();
    float acc = 0.0f;
#pragma unroll 8
    for (int d = 0; d < DD; d++) acc = fmaf(ws[d], X[(size_t)d * MM + m], acc);
    out[m] = acc;
}

// ---- stage 0b: split C,Q in [d][*] layout (consumers) ----
__global__ __launch_bounds__(256) void split_cq_kernel(const float* __restrict__ C,
                                                       const float* __restrict__ Q) {
    size_t i = ((size_t)blockIdx.x * 256 + threadIdx.x) * 4;
    const float* src; __nv_bfloat16 *dh, *dl;
    if (blockIdx.y == 0) { src = C; dh = g_Chi; dl = g_Clo; }
    else                 { src = Q; dh = g_Qhi; dl = g_Qlo; }
    float4 v = *(const float4*)(src + i);
    *(uint2*)(dh + i) = make_uint2(packsplit_hi(v.x, v.y), packsplit_hi(v.z, v.w));
    *(uint2*)(dl + i) = make_uint2(packsplit_lo(v.x, v.y), packsplit_lo(v.z, v.w));
}

// ---- stage 0c: transpose-split for s_mma ----
__global__ __launch_bounds__(256) void tsplit_kernel(const float* __restrict__ C,
                                                     const float* __restrict__ Q,
                                                     const float* __restrict__ W) {
    __shared__ float ts[32][33];
    __shared__ float wsc[32];
    int z = blockIdx.z, b = z >> 1, isQ = z & 1;
    int n0 = blockIdx.x * 32, d0 = blockIdx.y * 32;
    const float* X = (isQ ? Q : C) + (size_t)b * DD * NN;
    int t = threadIdx.x, nl = t & 31, dr = t >> 5;
    if (t < 32) wsc[t] = isQ ? W[b * 3 * DD + 2 * DD + d0 + t] : 1.0f;
#pragma unroll
    for (int k = 0; k < 4; k++)
        ts[dr + k * 8][nl] = X[(size_t)(d0 + dr + k * 8) * NN + n0 + nl];
    __syncthreads();
    int nr = t >> 3, dg = (t & 7) * 4;
    __nv_bfloat16* dh = (isQ ? g_QWhi : g_CThi) + ((size_t)b * NN + n0 + nr) * DD + d0 + dg;
    __nv_bfloat16* dl = (isQ ? g_QWlo : g_CTlo) + ((size_t)b * NN + n0 + nr) * DD + d0 + dg;
    float v0 = ts[dg][nr] * wsc[dg],     v1 = ts[dg + 1][nr] * wsc[dg + 1];
    float v2 = ts[dg + 2][nr] * wsc[dg + 2], v3 = ts[dg + 3][nr] * wsc[dg + 3];
    *(uint2*)dh = make_uint2(packsplit_hi(v0, v1), packsplit_hi(v2, v3));
    *(uint2*)dl = make_uint2(packsplit_lo(v0, v1), packsplit_lo(v2, v3));
}

// ---- stage 1: S = CT * QW^T via HMMA + biases + fused stats ----
#define G1_SMEM (1024 + 4 * 8192)
__global__ __launch_bounds__(256) void s_mma() {
    extern __shared__ char smc[];
    float* sc_s = (float*)smc;
    float* sq_s = (float*)(smc + 512);
    uint32_t* AH = (uint32_t*)(smc + 1024);
    uint32_t* AL = AH + T_WORDS;
    uint32_t* BH = AL + T_WORDS;
    uint32_t* BL = BH + T_WORDS;
    float* st  = (float*)(smc + 1024);
    float* rm4 = st;
    float* rfin = st + 512;
    float* rs4 = st + 640;
    float* cm2 = st + 1152;
    float* cfin = st + 1408;
    float* cs2 = st + 1536;
    int tid = threadIdx.x, lane = tid & 31, wid = tid >> 5;
    int b = blockIdx.z, n0 = blockIdx.y * 128, m0 = blockIdx.x * 128;
    if (tid < 128) { sc_s[tid] = g_sc[b * NN + n0 + tid]; sq_s[tid] = g_sq[b * MM + m0 + tid]; }
    const __nv_bfloat16* Ahg = g_CThi + ((size_t)b * NN + n0) * DD;
    const __nv_bfloat16* Alg = g_CTlo + ((size_t)b * NN + n0) * DD;
    const __nv_bfloat16* Bhg = g_QWhi + ((size_t)b * MM + m0) * DD;
    const __nv_bfloat16* Blg = g_QWlo + ((size_t)b * MM + m0) * DD;
    int wm = (wid & 1) * 64, wn = (wid >> 1) * 32;
    int g = lane >> 2, t4 = lane & 3;
    // ldmatrix per-lane constants
    int arow = lane & 15, achk = lane >> 4, aswz = (arow >> 1) & 3;
    int brow = lane & 7, bsel = (lane >> 4) & 1, bchk = (lane >> 3) & 1, bswz = (brow >> 1) & 3;
    uint32_t shAH = su32(AH), shAL = su32(AL), shBH = su32(BH), shBL = su32(BL);
    float acc[4][4][4] = {};
    int ar = tid >> 1, ac = (tid & 1) * 2, asw = (ar >> 1) & 3;
    __syncthreads();
    for (int c = 0; c < 4; c++) {
        const uint4* pah = (const uint4*)(Ahg + (size_t)ar * DD + c * 32);
        const uint4* pal = (const uint4*)(Alg + (size_t)ar * DD + c * 32);
        const uint4* pbh = (const uint4*)(Bhg + (size_t)ar * DD + c * 32);
        const uint4* pbl = (const uint4*)(Blg + (size_t)ar * DD + c * 32);
        ((uint4*)AH)[ar * 4 + (ac ^ asw)]       = pah[ac];
        ((uint4*)AH)[ar * 4 + ((ac + 1) ^ asw)] = pah[ac + 1];
        ((uint4*)AL)[ar * 4 + (ac ^ asw)]       = pal[ac];
        ((uint4*)AL)[ar * 4 + ((ac + 1) ^ asw)] = pal[ac + 1];
        ((uint4*)BH)[ar * 4 + (ac ^ asw)]       = pbh[ac];
        ((uint4*)BH)[ar * 4 + ((ac + 1) ^ asw)] = pbh[ac + 1];
        ((uint4*)BL)[ar * 4 + (ac ^ asw)]       = pbl[ac];
        ((uint4*)BL)[ar * 4 + ((ac + 1) ^ asw)] = pbl[ac + 1];
        __syncthreads();
#pragma unroll
        for (int ks = 0; ks < 2; ks++) {
            uint32_t bh[4][2], bl[4][2];
#pragma unroll
            for (int p = 0; p < 2; p++) {
                int j = wn + (2 * p + bsel) * 8 + brow;
                uint32_t off = (uint32_t)(j * 16 + (((ks * 2 + bchk) ^ bswz) << 2)) * 4;
                uint32_t r[4];
                ldsm4(r, shBH + off);
                bh[2 * p][0] = r[0]; bh[2 * p][1] = r[1];
                bh[2 * p + 1][0] = r[2]; bh[2 * p + 1][1] = r[3];
                ldsm4(r, shBL + off);
                bl[2 * p][0] = r[0]; bl[2 * p][1] = r[1];
                bl[2 * p + 1][0] = r[2]; bl[2 * p + 1][1] = r[3];
            }
#pragma unroll
            for (int mt = 0; mt < 4; mt++) {
                int row = wm + mt * 16 + arow;
                uint32_t off = (uint32_t)(row * 16 + (((ks * 2 + achk) ^ aswz) << 2)) * 4;
                uint32_t ah[4], al[4];
                ldsm4(ah, shAH + off);
                ldsm4(al, shAL + off);
#pragma unroll
                for (int nt = 0; nt < 4; nt++) {
                    mma16816(acc[mt][nt], ah, bh[nt]);
                    mma16816(acc[mt][nt], ah, bl[nt]);
                    mma16816(acc[mt][nt], al, bh[nt]);
                }
            }
        }
        __syncthreads();
    }
    float* Sb = g_S + (size_t)b * NN * MM;
#pragma unroll
    for (int mt = 0; mt < 4; mt++) {
#pragma unroll
        for (int nt = 0; nt < 4; nt++) {
            int r0 = wm + mt * 16 + g, c0 = wn + nt * 8 + t4 * 2;
            acc[mt][nt][0] += sc_s[r0] + sq_s[c0];
            acc[mt][nt][1] += sc_s[r0] + sq_s[c0 + 1];
            acc[mt][nt][2] += sc_s[r0 + 8] + sq_s[c0];
            acc[mt][nt][3] += sc_s[r0 + 8] + sq_s[c0 + 1];
            *(float2*)(Sb + (size_t)(n0 + r0) * MM + m0 + c0)     = make_float2(acc[mt][nt][0], acc[mt][nt][1]);
            *(float2*)(Sb + (size_t)(n0 + r0 + 8) * MM + m0 + c0) = make_float2(acc[mt][nt][2], acc[mt][nt][3]);
        }
    }
#pragma unroll
    for (int mt = 0; mt < 4; mt++) {
#pragma unroll
        for (int h = 0; h < 2; h++) {
            float m = acc[mt][0][h * 2];
#pragma unroll
            for (int nt = 0; nt < 4; nt++) {
                m = fmaxf(m, acc[mt][nt][h * 2]);
                m = fmaxf(m, acc[mt][nt][h * 2 + 1]);
            }
            m = fmaxf(m, __shfl_xor_sync(0xffffffffu, m, 1));
            m = fmaxf(m, __shfl_xor_sync(0xffffffffu, m, 2));
            if (t4 == 0) rm4[(wid >> 1) * 128 + wm + mt * 16 + g + 8 * h] = m;
        }
    }
    __syncthreads();
    if (tid < 128)
        rfin[tid] = fmaxf(fmaxf(rm4[tid], rm4[128 + tid]), fmaxf(rm4[256 + tid], rm4[384 + tid]));
    __syncthreads();
#pragma unroll
    for (int mt = 0; mt < 4; mt++) {
#pragma unroll
        for (int h = 0; h < 2; h++) {
            int r = wm + mt * 16 + g + 8 * h;
            float L = rfin[r], s = 0.0f;
#pragma unroll
            for (int nt = 0; nt < 4; nt++)
                s += fexp(acc[mt][nt][h * 2] - L) + fexp(acc[mt][nt][h * 2 + 1] - L);
            s += __shfl_xor_sync(0xffffffffu, s, 1);
            s += __shfl_xor_sync(0xffffffffu, s, 2);
            if (t4 == 0) rs4[(wid >> 1) * 128 + r] = s;
        }
    }
    __syncthreads();
    if (tid < 128)
        g_rowp[((size_t)(b * 16 + (m0 >> 7))) * NN + n0 + tid] =
            make_float2(rfin[tid], rs4[tid] + rs4[128 + tid] + rs4[256 + tid] + rs4[384 + tid]);
#pragma unroll
    for (int nt = 0; nt < 4; nt++) {
#pragma unroll
        for (int e = 0; e < 2; e++) {
            float m = acc[0][nt][e];
#pragma unroll
            for (int mt = 0; mt < 4; mt++) {
                m = fmaxf(m, acc[mt][nt][e]);
                m = fmaxf(m, acc[mt][nt][2 + e]);
            }
            m = fmaxf(m, __shfl_xor_sync(0xffffffffu, m, 4));
            m = fmaxf(m, __shfl_xor_sync(0xffffffffu, m, 8));
            m = fmaxf(m, __shfl_xor_sync(0xffffffffu, m, 16));
            if (g == 0) cm2[(wid & 1) * 128 + wn + nt * 8 + t4 * 2 + e] = m;
        }
    }
    __syncthreads();
    if (tid < 128) cfin[tid] = fmaxf(cm2[tid], cm2[128 + tid]);
    __syncthreads();
#pragma unroll
    for (int nt = 0; nt < 4; nt++) {
#pragma unroll
        for (int e = 0; e < 2; e++) {
            int c = wn + nt * 8 + t4 * 2 + e;
            float L = cfin[c], s = 0.0f;
#pragma unroll
            for (int mt = 0; mt < 4; mt++)
                s += fexp(acc[mt][nt][e] - L) + fexp(acc[mt][nt][2 + e] - L);
            s += __shfl_xor_sync(0xffffffffu, s, 4);
            s += __shfl_xor_sync(0xffffffffu, s, 8);
            s += __shfl_xor_sync(0xffffffffu, s, 16);
            if (g == 0) cs2[(wid & 1) * 128 + c] = s;
        }
    }
    __syncthreads();
    if (tid < 128)
        g_colp[((size_t)(b * 16 + (n0 >> 7))) * MM + m0 + tid] =
            make_float2(cfin[tid], cs2[tid] + cs2[128 + tid]);
}

// ---- stage 2: combines ----
__global__ __launch_bounds__(256) void rowcombine_kernel() {
    int idx = blockIdx.x * 256 + threadIdx.x;
    int b = idx >> 11, n = idx & (NN - 1);
    const float2* p = g_rowp + (size_t)(b * 16) * NN + n;
    float2 f = p[0]; float mx = f.x, s = f.y;
#pragma unroll
    for (int t = 1; t < 16; t++) {
        float2 g = p[(size_t)t * NN];
        float nm = fmaxf(mx, g.x);
        s = s * __expf(mx - nm) + g.y * __expf(g.x - nm); mx = nm;
    }
    g_L1[idx] = mx + logf(s);
}
__global__ __launch_bounds__(256) void colcombine_kernel() {
    int idx = blockIdx.x * 256 + threadIdx.x;
    int b = idx >> 11, m = idx & (MM - 1);
    const float2* p = g_colp + (size_t)(b * 16) * MM + m;
    float2 f = p[0]; float mx = f.x, s = f.y;
#pragma unroll
    for (int t = 1; t < 16; t++) {
        float2 g = p[(size_t)t * MM];
        float nm = fmaxf(mx, g.x);
        s = s * __expf(mx - nm) + g.y * __expf(g.x - nm); mx = nm;
    }
    g_L2[idx] = mx + logf(s);
}

// ---- stage 3: CB = C * E2 via HMMA ----
__global__ __launch_bounds__(256) void cb_mma() {
    extern __shared__ char smc[];
    float* l2s = (float*)smc;
    uint32_t* AH = (uint32_t*)(smc + 512);
    uint32_t* AL = AH + T_WORDS;
    uint32_t* EH = AL + T_WORDS;
    uint32_t* EL = EH + T_WORDS;
    int tid = threadIdx.x, lane = tid & 31, wid = tid >> 5;
    int b = blockIdx.y, m0 = blockIdx.x * 128;
    if (tid < 128) l2s[tid] = g_L2[b * MM + m0 + tid];
    const float* Sb = g_S + (size_t)b * NN * MM;
    const __nv_bfloat16* Ch = g_Chi + (size_t)b * DD * NN;
    const __nv_bfloat16* Cl = g_Clo + (size_t)b * DD * NN;
    int wm = (wid & 1) * 64, wn = (wid >> 1) * 32;
    int g = lane >> 2, t4 = lane & 3;
    int arow = lane & 15, achk = lane >> 4, aswz = (arow >> 1) & 3;
    int brow = lane & 7, bsel = (lane >> 4) & 1, bchk = (lane >> 3) & 1, bswz = (brow >> 1) & 3;
    uint32_t shAH = su32(AH), shAL = su32(AL), shEH = su32(EH), shEL = su32(EL);
    float acc[4][4][4] = {};
    int ar = tid >> 1, ac = (tid & 1) * 2, asw = (ar >> 1) & 3;
    int kp = tid & 15, mb = tid >> 4;
    __syncthreads();
    for (int c = 0; c < NN / KB; c++) {
        int n0 = c * KB;
        {
            const uint4* ph = (const uint4*)(Ch + (size_t)ar * NN + n0);
            const uint4* pl = (const uint4*)(Cl + (size_t)ar * NN + n0);
            ((uint4*)AH)[ar * 4 + (ac ^ asw)]       = ph[ac];
            ((uint4*)AH)[ar * 4 + ((ac + 1) ^ asw)] = ph[ac + 1];
            ((uint4*)AL)[ar * 4 + (ac ^ asw)]       = pl[ac];
            ((uint4*)AL)[ar * 4 + ((ac + 1) ^ asw)] = pl[ac + 1];
        }
        {
            const float* s0 = Sb + (size_t)(n0 + 2 * kp) * MM + m0 + mb * 8;
            const float* s1 = s0 + MM;
            float4 x0 = *(const float4*)s0, x1 = *(const float4*)(s0 + 4);
            float4 y0 = *(const float4*)s1, y1 = *(const float4*)(s1 + 4);
            float xs[8] = {x0.x, x0.y, x0.z, x0.w, x1.x, x1.y, x1.z, x1.w};
            float ys[8] = {y0.x, y0.y, y0.z, y0.w, y1.x, y1.y, y1.z, y1.w};
#pragma unroll
            for (int i = 0; i < 8; i++) {
                int m = mb * 8 + i;
                float L = l2s[m];
                float e0 = fexp(xs[i] - L), e1 = fexp(ys[i] - L);
                int w = m * 16 + (kp ^ (((m >> 1) & 3) << 2));
                EH[w] = packsplit_hi(e0, e1);
                EL[w] = packsplit_lo(e0, e1);
            }
        }
        __syncthreads();
#pragma unroll
        for (int ks = 0; ks < 2; ks++) {
            uint32_t bh[4][2], bl[4][2];
#pragma unroll
            for (int p = 0; p < 2; p++) {
                int j = wn + (2 * p + bsel) * 8 + brow;
                uint32_t off = (uint32_t)(j * 16 + (((ks * 2 + bchk) ^ bswz) << 2)) * 4;
                uint32_t r[4];
                ldsm4(r, shEH + off);
                bh[2 * p][0] = r[0]; bh[2 * p][1] = r[1];
                bh[2 * p + 1][0] = r[2]; bh[2 * p + 1][1] = r[3];
                ldsm4(r, shEL + off);
                bl[2 * p][0] = r[0]; bl[2 * p][1] = r[1];
                bl[2 * p + 1][0] = r[2]; bl[2 * p + 1][1] = r[3];
            }
#pragma unroll
            for (int mt = 0; mt < 4; mt++) {
                int row = wm + mt * 16 + arow;
                uint32_t off = (uint32_t)(row * 16 + (((ks * 2 + achk) ^ aswz) << 2)) * 4;
                uint32_t ah[4], al[4];
                ldsm4(ah, shAH + off);
                ldsm4(al, shAL + off);
#pragma unroll
                for (int nt = 0; nt < 4; nt++) {
                    mma16816(acc[mt][nt], ah, bh[nt]);
                    mma16816(acc[mt][nt], ah, bl[nt]);
                    mma16816(acc[mt][nt], al, bh[nt]);
                }
            }
        }
        __syncthreads();
    }
#pragma unroll
    for (int mt = 0; mt < 4; mt++) {
#pragma unroll
        for (int nt = 0; nt < 4; nt++) {
            float* cfr = acc[mt][nt];
            int d0 = wm + mt * 16 + g;
            int col = m0 + wn + nt * 8 + t4 * 2;
            size_t o0 = (size_t)(b * DD + d0) * MM + col;
            size_t o1 = (size_t)(b * DD + d0 + 8) * MM + col;
            *(uint32_t*)(g_CBhi + o0) = packsplit_hi(cfr[0], cfr[1]);
            *(uint32_t*)(g_CBlo + o0) = packsplit_lo(cfr[0], cfr[1]);
            *(uint32_t*)(g_CBhi + o1) = packsplit_hi(cfr[2], cfr[3]);
            *(uint32_t*)(g_CBlo + o1) = packsplit_lo(cfr[2], cfr[3]);
        }
    }
}

// ---- stage 4: fused A + Bt (128x64 slab of both outputs) ----
#define ABF_SMEM (512 + 4 * 8192 + 2 * 4096)
__global__ __launch_bounds__(256) void abf_mma() {
    extern __shared__ char smc[];
    float* l1s = (float*)smc;
    uint32_t* QH = (uint32_t*)(smc + 512);
    uint32_t* QL = QH + 2048;
    uint32_t* BH = QL + 2048;
    uint32_t* BL = BH + 2048;
    uint32_t* EH = BL + 2048;
    uint32_t* EL = EH + 1024;
    int tid = threadIdx.x, lane = tid & 31, wid = tid >> 5;
    int b = blockIdx.y, n0 = blockIdx.x * 64;
    if (tid < 64) l1s[tid] = g_L1[b * NN + n0 + tid];
    const float* Sb = g_S + (size_t)b * NN * MM;
    const __nv_bfloat16* Qh = g_Qhi + (size_t)b * DD * MM;
    const __nv_bfloat16* Ql = g_Qlo + (size_t)b * DD * MM;
    const __nv_bfloat16* Bh = g_CBhi + (size_t)b * DD * MM;
    const __nv_bfloat16* Bl = g_CBlo + (size_t)b * DD * MM;
    int isBt = wid >> 2, wg = wid & 3;
    int wm = (wg & 1) * 64, wn = (wg >> 1) * 32;
    int g = lane >> 2, t4 = lane & 3;
    int arow = lane & 15, achk = lane >> 4, aswz = (arow >> 1) & 3;
    int brow = lane & 7, bsel = (lane >> 4) & 1, bchk = (lane >> 3) & 1, bswz = (brow >> 1) & 3;
    uint32_t shXH = isBt ? su32(BH) : su32(QH);
    uint32_t shXL = isBt ? su32(BL) : su32(QL);
    uint32_t shEH = su32(EH), shEL = su32(EL);
    float acc[4][4][4] = {};
    int ar = tid >> 1, ac = (tid & 1) * 2, asw = (ar >> 1) & 3;
    int nr = tid >> 2, q4 = tid & 3;
    __syncthreads();
    for (int c = 0; c < MM / KB; c++) {
        int mc0 = c * KB;
        {
            const uint4* pqh = (const uint4*)(Qh + (size_t)ar * MM + mc0);
            const uint4* pql = (const uint4*)(Ql + (size_t)ar * MM + mc0);
            const uint4* pbh = (const uint4*)(Bh + (size_t)ar * MM + mc0);
            const uint4* pbl = (const uint4*)(Bl + (size_t)ar * MM + mc0);
            ((uint4*)QH)[ar * 4 + (ac ^ asw)]       = pqh[ac];
            ((uint4*)QH)[ar * 4 + ((ac + 1) ^ asw)] = pqh[ac + 1];
            ((uint4*)QL)[ar * 4 + (ac ^ asw)]       = pql[ac];
            ((uint4*)QL)[ar * 4 + ((ac + 1) ^ asw)] = pql[ac + 1];
            ((uint4*)BH)[ar * 4 + (ac ^ asw)]       = pbh[ac];
            ((uint4*)BH)[ar * 4 + ((ac + 1) ^ asw)] = pbh[ac + 1];
            ((uint4*)BL)[ar * 4 + (ac ^ asw)]       = pbl[ac];
            ((uint4*)BL)[ar * 4 + ((ac + 1) ^ asw)] = pbl[ac + 1];
        }
        {
            const float* sp = Sb + (size_t)(n0 + nr) * MM + mc0 + q4 * 8;
            float4 v0 = *(const float4*)sp, v1 = *(const float4*)(sp + 4);
            float vs[8] = {v0.x, v0.y, v0.z, v0.w, v1.x, v1.y, v1.z, v1.w};
            float L = l1s[nr];
            int sn = ((nr >> 1) & 3) << 2;
#pragma unroll
            for (int j = 0; j < 4; j++) {
                float e0 = fexp(vs[2 * j] - L), e1 = fexp(vs[2 * j + 1] - L);
                int w = nr * 16 + ((q4 * 4 + j) ^ sn);
                EH[w] = packsplit_hi(e0, e1);
                EL[w] = packsplit_lo(e0, e1);
            }
        }
        __syncthreads();
#pragma unroll
        for (int ks = 0; ks < 2; ks++) {
            uint32_t bh[4][2], bl[4][2];
#pragma unroll
            for (int p = 0; p < 2; p++) {
                int j = wn + (2 * p + bsel) * 8 + brow;
                uint32_t off = (uint32_t)(j * 16 + (((ks * 2 + bchk) ^ bswz) << 2)) * 4;
                uint32_t r[4];
                ldsm4(r, shEH + off);
                bh[2 * p][0] = r[0]; bh[2 * p][1] = r[1];
                bh[2 * p + 1][0] = r[2]; bh[2 * p + 1][1] = r[3];
                ldsm4(r, shEL + off);
                bl[2 * p][0] = r[0]; bl[2 * p][1] = r[1];
                bl[2 * p + 1][0] = r[2]; bl[2 * p + 1][1] = r[3];
            }
#pragma unroll
            for (int mt = 0; mt < 4; mt++) {
                int row = wm + mt * 16 + arow;
                uint32_t off = (uint32_t)(row * 16 + (((ks * 2 + achk) ^ aswz) << 2)) * 4;
                uint32_t ah[4], al[4];
                ldsm4(ah, shXH + off);
                ldsm4(al, shXL + off);
#pragma unroll
                for (int nt = 0; nt < 4; nt++) {
                    mma16816(acc[mt][nt], ah, bh[nt]);
                    mma16816(acc[mt][nt], ah, bl[nt]);
                    mma16816(acc[mt][nt], al, bh[nt]);
                }
            }
        }
        __syncthreads();
    }
    float* Out = (isBt ? g_Bt : g_A) + (size_t)b * DD * NN;
#pragma unroll
    for (int mt = 0; mt < 4; mt++) {
#pragma unroll
        for (int nt = 0; nt < 4; nt++) {
            float* cfr = acc[mt][nt];
            int r0 = wm + mt * 16 + g;
            int col = n0 + wn + nt * 8 + t4 * 2;
            *(float2*)(Out + (size_t)r0 * NN + col)       = make_float2(cfr[0], cfr[1]);
            *(float2*)(Out + (size_t)(r0 + 8) * NN + col) = make_float2(cfr[2], cfr[3]);
        }
    }
}

// ---- stage 5: concat + dropout ----
__device__ __forceinline__ void write_drop4(float* p, size_t idx, float4 v) {
    float4 o;
    o.x = dropscale((uint32_t)(idx + 0), v.x);
    o.y = dropscale((uint32_t)(idx + 1), v.y);
    o.z = dropscale((uint32_t)(idx + 2), v.z);
    o.w = dropscale((uint32_t)(idx + 3), v.w);
    *(float4*)p = o;
}
__global__ __launch_bounds__(256) void epilogue_kernel(const float* __restrict__ C,
                                                       float* __restrict__ out) {
    unsigned gi = blockIdx.x * 256u + threadIdx.x;
    unsigned t = gi & 511u, bd = gi >> 9, d = bd & 127u, b = bd >> 7, n = t * 4u;
    size_t src = ((size_t)(b * DD + d)) * NN + n;
    float4 c = *(const float4*)(C + src);
    float4 a = *(const float4*)(g_A + src);
    float4 bt = *(const float4*)(g_Bt + src);
    float4 ca = make_float4(c.x * a.x, c.y * a.y, c.z * a.z, c.w * a.w);
    float4 cbt = make_float4(c.x * bt.x, c.y * bt.y, c.z * bt.z, c.w * bt.w);
    size_t o0 = ((size_t)b * 4 * DD + d) * NN + n;
    const size_t st = (size_t)DD * NN;
    write_drop4(out + o0, o0, c);
    write_drop4(out + o0 + st, o0 + st, a);
    write_drop4(out + o0 + 2 * st, o0 + 2 * st, ca);
    write_drop4(out + o0 + 3 * st, o0 + 3 * st, cbt);
}

// ---- launch ----
#define MMA_SMEM (512 + 4 * 8192)
extern "C" void kernel_launch(void* const* d_in, const int* in_sizes, int n_in,
                              void* d_out, int out_size) {
    const float* C = (const float*)d_in[0];
    const float* Q = (const float*)d_in[1];
    const float* W = (const float*)d_in[2];
    float* out = (float*)d_out;
    bias_kernel<<<dim3(MM / 256, BB, 2), 256>>>(C, Q, W);
    split_cq_kernel<<<dim3((BB * DD * NN / 4) / 256, 2), 256>>>(C, Q);
    tsplit_kernel<<<dim3(NN / 32, DD / 32, BB * 2), 256>>>(C, Q, W);
    s_mma<<<dim3(MM / 128, NN / 128, BB), 256, G1_SMEM>>>();
    rowcombine_kernel<<<dim3((BB * NN) / 256), 256>>>();
    colcombine_kernel<<<dim3((BB * MM) / 256), 256>>>();
    cb_mma<<<dim3(MM / 128, BB), 256, MMA_SMEM>>>();
    abf_mma<<<dim3(NN / 64, BB), 256, ABF_SMEM>>>();
    epilogue_kernel<<<dim3((BB * DD * NN / 4) / 256), 256>>>(C, out);
}